// round 1
// baseline (speedup 1.0000x reference)
#include <cuda_runtime.h>
#include <cstdint>

#define NTOK 49
#define MPAD 64
#define DIM 128
#define HEADS 4
#define HD 32
#define NWIN 64
#define NBLK 4096
#define XS 132   // padded stride for 64x128 fp32 tiles
#define WS 132   // padded stride for 128x128 weight tile
#define PS 66    // padded stride for 64x64 softmax-P tiles

// 4 * 64 * 64 fp32, zero-padded outside 49x49
__device__ float g_relBias[HEADS * MPAD * MPAD];

__global__ void relbias_kernel(const float* __restrict__ bias_table,
                               const int* __restrict__ rel_index)
{
    int idx = blockIdx.x * blockDim.x + threadIdx.x;
    if (idx >= HEADS * MPAD * MPAD) return;
    int c = idx & (MPAD - 1);
    int r = (idx >> 6) & (MPAD - 1);
    int h = idx >> 12;
    float v = 0.f;
    if (r < NTOK && c < NTOK)
        v = bias_table[rel_index[r * NTOK + c] * HEADS + h];
    g_relBias[idx] = v;
}

__device__ __forceinline__ float to_tf32(float x) {
    asm("cvt.rna.tf32.f32 %0, %0;" : "+f"(x));
    return x;
}

__device__ __forceinline__ void mma8(float c[4], const uint32_t a[4], const uint32_t b[2]) {
    asm volatile(
        "mma.sync.aligned.m16n8k8.row.col.f32.tf32.tf32.f32 "
        "{%0,%1,%2,%3}, {%4,%5,%6,%7}, {%8,%9}, {%0,%1,%2,%3};\n"
        : "+f"(c[0]), "+f"(c[1]), "+f"(c[2]), "+f"(c[3])
        : "r"(a[0]), "r"(a[1]), "r"(a[2]), "r"(a[3]), "r"(b[0]), "r"(b[1]));
}

__device__ __forceinline__ uint32_t fu(float x) { return __float_as_uint(x); }

// stage a [49,128] fp32 tile from global into padded smem [64][XS], tf32-rounded,
// rows 49..63 zeroed
__device__ __forceinline__ void load_x(float* sX, const float* __restrict__ gX, int tid) {
    for (int i = tid; i < NTOK * 32; i += 256) {
        int r = i >> 5, c4 = i & 31;
        float4 v = reinterpret_cast<const float4*>(gX)[i];
        float* d = sX + r * XS + c4 * 4;
        d[0] = to_tf32(v.x); d[1] = to_tf32(v.y); d[2] = to_tf32(v.z); d[3] = to_tf32(v.w);
    }
    for (int i = tid; i < (MPAD - NTOK) * 32; i += 256) {
        int r = NTOK + (i >> 5), c4 = i & 31;
        float4 z = make_float4(0.f, 0.f, 0.f, 0.f);
        *reinterpret_cast<float4*>(sX + r * XS + c4 * 4) = z;
    }
}

// stage a [128,128] fp32 weight from global into padded smem [128][WS], tf32-rounded
__device__ __forceinline__ void load_w(float* sW, const float* __restrict__ gW, int tid) {
    for (int i = tid; i < 128 * 32; i += 256) {
        int r = i >> 5, c4 = i & 31;
        float4 v = reinterpret_cast<const float4*>(gW)[i];
        float* d = sW + r * WS + c4 * 4;
        d[0] = to_tf32(v.x); d[1] = to_tf32(v.y); d[2] = to_tf32(v.z); d[3] = to_tf32(v.w);
    }
}

// C[64,128] = A[64,128] @ W^T + bias  (W given row-major [n_out][k])
// 8 warps: warp handles rows [16*(w&3),+16) x cols [64*(w>>2),+64)
template <bool TOGLOBAL>
__device__ __forceinline__ void gemm_64_128_128(
    const float* __restrict__ sA, const float* __restrict__ sWm,
    const float* __restrict__ bias, float* __restrict__ dst, int warp, int lane)
{
    const int g = lane >> 2, tg = lane & 3;
    const int mBase = (warp & 3) * 16;
    const int nBase = (warp >> 2) * 64;
    float acc[8][4];
    #pragma unroll
    for (int i = 0; i < 8; i++)
        #pragma unroll
        for (int j = 0; j < 4; j++) acc[i][j] = 0.f;

    #pragma unroll
    for (int kk = 0; kk < 16; kk++) {
        const int k = kk * 8;
        uint32_t a[4];
        const float* Ap = sA + (mBase + g) * XS + k + tg;
        a[0] = fu(Ap[0]);
        a[1] = fu(Ap[8 * XS]);
        a[2] = fu(Ap[4]);
        a[3] = fu(Ap[8 * XS + 4]);
        #pragma unroll
        for (int nt = 0; nt < 8; nt++) {
            const float* Bp = sWm + (nBase + nt * 8 + g) * WS + k + tg;
            uint32_t bfr[2];
            bfr[0] = fu(Bp[0]);
            bfr[1] = fu(Bp[4]);
            mma8(acc[nt], a, bfr);
        }
    }
    const int r0 = mBase + g, r1 = r0 + 8;
    #pragma unroll
    for (int nt = 0; nt < 8; nt++) {
        const int c = nBase + nt * 8 + 2 * tg;
        const float b0 = bias[c], b1 = bias[c + 1];
        if (TOGLOBAL) {
            if (r0 < NTOK) {
                float2 v = make_float2(acc[nt][0] + b0, acc[nt][1] + b1);
                *reinterpret_cast<float2*>(dst + r0 * DIM + c) = v;
            }
            if (r1 < NTOK) {
                float2 v = make_float2(acc[nt][2] + b0, acc[nt][3] + b1);
                *reinterpret_cast<float2*>(dst + r1 * DIM + c) = v;
            }
        } else {
            float2 v0 = make_float2(to_tf32(acc[nt][0] + b0), to_tf32(acc[nt][1] + b1));
            *reinterpret_cast<float2*>(dst + r0 * XS + c) = v0;
            float2 v1 = make_float2(to_tf32(acc[nt][2] + b0), to_tf32(acc[nt][3] + b1));
            *reinterpret_cast<float2*>(dst + r1 * XS + c) = v1;
        }
    }
}

__global__ __launch_bounds__(256, 1)
void swin_fused_kernel(const float* __restrict__ query, const float* __restrict__ key,
                       const float* __restrict__ value,
                       const float* __restrict__ Wq, const float* __restrict__ bq,
                       const float* __restrict__ Wk, const float* __restrict__ bk,
                       const float* __restrict__ Wv, const float* __restrict__ bv,
                       const float* __restrict__ Wp, const float* __restrict__ bp,
                       const float* __restrict__ mask, float* __restrict__ out)
{
    extern __shared__ float smem[];
    float* sX = smem;                 // 64 x XS   (input staging, later O)
    float* sW = sX + MPAD * XS;       // 128 x WS  (weights, later softmax P: 4 x 64 x PS)
    float* sQ = sW + DIM * WS;        // 64 x XS
    float* sK = sQ + MPAD * XS;       // 64 x XS
    float* sV = sK + MPAD * XS;       // 64 x XS
    float* sB = sV + MPAD * XS;       // 4 x 128 biases

    const int tid = threadIdx.x;
    const int warp = tid >> 5, lane = tid & 31;
    const int b = blockIdx.x;
    const int base = b * NTOK * DIM;

    // stage biases once
    for (int i = tid; i < DIM; i += 256) {
        sB[i]           = bq[i];
        sB[DIM + i]     = bk[i];
        sB[2 * DIM + i] = bv[i];
        sB[3 * DIM + i] = bp[i];
    }

    // ---- q projection ----
    load_w(sW, Wq, tid);
    load_x(sX, query + base, tid);
    __syncthreads();
    gemm_64_128_128<false>(sX, sW, sB, sQ, warp, lane);
    __syncthreads();

    // ---- k projection ----
    load_w(sW, Wk, tid);
    load_x(sX, key + base, tid);
    __syncthreads();
    gemm_64_128_128<false>(sX, sW, sB + DIM, sK, warp, lane);
    __syncthreads();

    // ---- v projection ----
    load_w(sW, Wv, tid);
    load_x(sX, value + base, tid);
    __syncthreads();
    gemm_64_128_128<false>(sX, sW, sB + 2 * DIM, sV, warp, lane);
    __syncthreads();

    // ---- attention: per head, 2 warps (32 rows each) ----
    const int g = lane >> 2, tg = lane & 3;
    const int h = warp >> 1;
    const int mB = (warp & 1) * 32;

    float accS[2][8][4];
    #pragma unroll
    for (int mt = 0; mt < 2; mt++)
        #pragma unroll
        for (int nt = 0; nt < 8; nt++)
            #pragma unroll
            for (int j = 0; j < 4; j++) accS[mt][nt][j] = 0.f;

    #pragma unroll
    for (int kk = 0; kk < 4; kk++) {
        const int k = h * HD + kk * 8;
        uint32_t a[2][4];
        #pragma unroll
        for (int mt = 0; mt < 2; mt++) {
            const float* Ap = sQ + (mB + mt * 16 + g) * XS + k + tg;
            a[mt][0] = fu(Ap[0]);
            a[mt][1] = fu(Ap[8 * XS]);
            a[mt][2] = fu(Ap[4]);
            a[mt][3] = fu(Ap[8 * XS + 4]);
        }
        #pragma unroll
        for (int nt = 0; nt < 8; nt++) {
            const float* Bp = sK + (nt * 8 + g) * XS + k + tg;
            uint32_t bfr[2];
            bfr[0] = fu(Bp[0]);
            bfr[1] = fu(Bp[4]);
            mma8(accS[0][nt], a[0], bfr);
            mma8(accS[1][nt], a[1], bfr);
        }
    }

    // ---- bias + mask + softmax, write P into sW region ----
    const float scale = 0.17677669529663687f;  // 1/sqrt(32)
    const float* maskp = mask + (b & (NWIN - 1)) * NTOK * NTOK;
    float* Ph = sW + h * MPAD * PS;

    #pragma unroll
    for (int mt = 0; mt < 2; mt++) {
        #pragma unroll
        for (int rs = 0; rs < 2; rs++) {
            const int r = mB + mt * 16 + rs * 8 + g;
            float lv[16];
            #pragma unroll
            for (int nt = 0; nt < 8; nt++) {
                #pragma unroll
                for (int j = 0; j < 2; j++) {
                    const int c = nt * 8 + 2 * tg + j;
                    float l = accS[mt][nt][rs * 2 + j] * scale;
                    if (c >= NTOK) l = -1e30f;
                    else if (r < NTOK)
                        l += g_relBias[(h * MPAD + r) * MPAD + c] + maskp[r * NTOK + c];
                    lv[nt * 2 + j] = l;
                }
            }
            float m = lv[0];
            #pragma unroll
            for (int i = 1; i < 16; i++) m = fmaxf(m, lv[i]);
            m = fmaxf(m, __shfl_xor_sync(0xffffffffu, m, 1));
            m = fmaxf(m, __shfl_xor_sync(0xffffffffu, m, 2));
            float s = 0.f;
            #pragma unroll
            for (int i = 0; i < 16; i++) { lv[i] = __expf(lv[i] - m); s += lv[i]; }
            s += __shfl_xor_sync(0xffffffffu, s, 1);
            s += __shfl_xor_sync(0xffffffffu, s, 2);
            const float inv = 1.f / s;
            #pragma unroll
            for (int nt = 0; nt < 8; nt++) {
                float2 v = make_float2(to_tf32(lv[nt * 2] * inv), to_tf32(lv[nt * 2 + 1] * inv));
                *reinterpret_cast<float2*>(Ph + r * PS + nt * 8 + 2 * tg) = v;
            }
        }
    }
    __syncthreads();

    // ---- PV: O[64,32h..] = P @ V_h ----
    float accO[2][4][4];
    #pragma unroll
    for (int mt = 0; mt < 2; mt++)
        #pragma unroll
        for (int nt = 0; nt < 4; nt++)
            #pragma unroll
            for (int j = 0; j < 4; j++) accO[mt][nt][j] = 0.f;

    #pragma unroll
    for (int kk = 0; kk < 8; kk++) {
        const int k = kk * 8;
        uint32_t a[2][4];
        #pragma unroll
        for (int mt = 0; mt < 2; mt++) {
            const float* Ap = Ph + (mB + mt * 16 + g) * PS + k + tg;
            a[mt][0] = fu(Ap[0]);
            a[mt][1] = fu(Ap[8 * PS]);
            a[mt][2] = fu(Ap[4]);
            a[mt][3] = fu(Ap[8 * PS + 4]);
        }
        #pragma unroll
        for (int nt = 0; nt < 4; nt++) {
            const float* Bp = sV + (k + tg) * XS + h * HD + nt * 8 + g;
            uint32_t bfr[2];
            bfr[0] = fu(Bp[0]);
            bfr[1] = fu(Bp[4 * XS]);
            mma8(accO[0][nt], a[0], bfr);
            mma8(accO[1][nt], a[1], bfr);
        }
    }

    // store O into sX (free since v projection)
    #pragma unroll
    for (int mt = 0; mt < 2; mt++) {
        #pragma unroll
        for (int nt = 0; nt < 4; nt++) {
            const int c = h * HD + nt * 8 + 2 * tg;
            const int r0 = mB + mt * 16 + g, r1 = r0 + 8;
            float2 v0 = make_float2(to_tf32(accO[mt][nt][0]), to_tf32(accO[mt][nt][1]));
            *reinterpret_cast<float2*>(sX + r0 * XS + c) = v0;
            float2 v1 = make_float2(to_tf32(accO[mt][nt][2]), to_tf32(accO[mt][nt][3]));
            *reinterpret_cast<float2*>(sX + r1 * XS + c) = v1;
        }
    }
    __syncthreads();  // all warps done reading P (sW) and writing O (sX)

    // ---- output projection ----
    load_w(sW, Wp, tid);
    __syncthreads();
    gemm_64_128_128<true>(sX, sW, sB + 3 * DIM, out + base, warp, lane);
}

#define SMEM_BYTES ((MPAD * XS + DIM * WS + 3 * (MPAD * XS) + 4 * DIM) * 4)

extern "C" void kernel_launch(void* const* d_in, const int* in_sizes, int n_in,
                              void* d_out, int out_size)
{
    const float* query      = (const float*)d_in[0];
    const float* key        = (const float*)d_in[1];
    const float* value      = (const float*)d_in[2];
    const float* Wq         = (const float*)d_in[3];
    const float* bq         = (const float*)d_in[4];
    const float* Wk         = (const float*)d_in[5];
    const float* bk         = (const float*)d_in[6];
    const float* Wv         = (const float*)d_in[7];
    const float* bv         = (const float*)d_in[8];
    const float* bias_table = (const float*)d_in[9];
    const float* Wp         = (const float*)d_in[10];
    const float* bp         = (const float*)d_in[11];
    const float* mask       = (const float*)d_in[12];
    const int*   rel_index  = (const int*)d_in[13];
    float* out = (float*)d_out;

    relbias_kernel<<<(HEADS * MPAD * MPAD + 255) / 256, 256>>>(bias_table, rel_index);

    cudaFuncSetAttribute(swin_fused_kernel,
                         cudaFuncAttributeMaxDynamicSharedMemorySize, SMEM_BYTES);
    swin_fused_kernel<<<NBLK, 256, SMEM_BYTES>>>(
        query, key, value, Wq, bq, Wk, bk, Wv, bv, Wp, bp, mask, out);
}

// round 4
// speedup vs baseline: 1.8042x; 1.8042x over previous
#include <cuda_runtime.h>
#include <cstdint>

#define NTOK 49
#define MPAD 64
#define DIM 128
#define HEADS 4
#define HD 32
#define NWIN 64
#define NBLK 4096
#define NROWS (NBLK * NTOK)          // 200704
#define XS 132   // padded stride for 64x128 attn tiles
#define PS 66    // padded stride for 64x64 softmax-P tiles
#define XS2 132  // proj input tile stride
#define WS2 36   // proj weight k-chunk stride (32 + 4 pad)

// ---------------- global scratch (allocation-free) ----------------
__device__ float g_q[NROWS * DIM];
__device__ float g_k[NROWS * DIM];
__device__ float g_v[NROWS * DIM];
__device__ float g_x2[NROWS * DIM];
__device__ float g_relBias[HEADS * MPAD * MPAD];

__global__ void relbias_kernel(const float* __restrict__ bias_table,
                               const int* __restrict__ rel_index)
{
    int idx = blockIdx.x * blockDim.x + threadIdx.x;
    if (idx >= HEADS * MPAD * MPAD) return;
    int c = idx & (MPAD - 1);
    int r = (idx >> 6) & (MPAD - 1);
    int h = idx >> 12;
    float v = 0.f;
    if (r < NTOK && c < NTOK)
        v = bias_table[rel_index[r * NTOK + c] * HEADS + h];
    g_relBias[idx] = v;
}

__device__ __forceinline__ float to_tf32(float x) {
    asm("cvt.rna.tf32.f32 %0, %0;" : "+f"(x));
    return x;
}
__device__ __forceinline__ uint32_t fu(float x) { return __float_as_uint(x); }

__device__ __forceinline__ void mma8(float c[4], const uint32_t a[4], const uint32_t b[2]) {
    asm volatile(
        "mma.sync.aligned.m16n8k8.row.col.f32.tf32.tf32.f32 "
        "{%0,%1,%2,%3}, {%4,%5,%6,%7}, {%8,%9}, {%0,%1,%2,%3};\n"
        : "+f"(c[0]), "+f"(c[1]), "+f"(c[2]), "+f"(c[3])
        : "r"(a[0]), "r"(a[1]), "r"(a[2]), "r"(a[3]), "r"(b[0]), "r"(b[1]));
}

// =====================================================================
// Projection GEMM: O[m, n] = (X[m, :] @ W[n, :] + bias[n]) * alpha
// M = 200704, N = K = 128. Grid (1568, nz). M-tile 128. 256 threads.
// smem: X tile 128x132, W double-buffered k-chunks 2 x 128x36. 2 CTAs/SM.
// =====================================================================
__global__ __launch_bounds__(256, 2)
void proj_kernel(const float* __restrict__ X0, const float* __restrict__ X1,
                 const float* __restrict__ X2,
                 const float* __restrict__ W0_, const float* __restrict__ W1_,
                 const float* __restrict__ W2_,
                 const float* __restrict__ B0_, const float* __restrict__ B1_,
                 const float* __restrict__ B2_,
                 float* __restrict__ O0_, float* __restrict__ O1_,
                 float* __restrict__ O2_,
                 float a0, float a1, float a2)
{
    extern __shared__ float sm[];
    float* sX = sm;                   // 128 x 132
    float* sW = sX + 128 * XS2;       // 2 x 128 x 36

    const float* X; const float* W; const float* Bb; float* O; float alpha;
    if (blockIdx.y == 0)      { X = X0; W = W0_; Bb = B0_; O = O0_; alpha = a0; }
    else if (blockIdx.y == 1) { X = X1; W = W1_; Bb = B1_; O = O1_; alpha = a1; }
    else                      { X = X2; W = W2_; Bb = B2_; O = O2_; alpha = a2; }

    const int tid  = threadIdx.x;
    const int warp = tid >> 5, lane = tid & 31;
    const int g = lane >> 2, tg = lane & 3;
    const int mBase = blockIdx.x * 128;

    // ---- stage X tile (tf32-rounded) ----
    const float4* gX = reinterpret_cast<const float4*>(X + mBase * DIM);
    #pragma unroll
    for (int t = 0; t < 16; t++) {
        int f = t * 256 + tid;
        int r = f >> 5, c4 = f & 31;
        float4 v = gX[f];
        float* d = sX + r * XS2 + c4 * 4;
        d[0] = to_tf32(v.x); d[1] = to_tf32(v.y);
        d[2] = to_tf32(v.z); d[3] = to_tf32(v.w);
    }
    // ---- W chunk 0 -> buffer 0 ----
    const float4* gW = reinterpret_cast<const float4*>(W);
    #pragma unroll
    for (int t = 0; t < 4; t++) {
        int f = t * 256 + tid;
        int n = f >> 3, c4 = f & 7;
        float4 v = gW[n * 32 + c4];                 // chunk 0: cols 0..31
        float* d = sW + n * WS2 + c4 * 4;
        d[0] = to_tf32(v.x); d[1] = to_tf32(v.y);
        d[2] = to_tf32(v.z); d[3] = to_tf32(v.w);
    }
    __syncthreads();

    const int wm = warp & 3;     // 4 m-chunks of 32 rows
    const int wn = warp >> 2;    // 2 n-chunks of 64 cols
    float acc[2][8][4];
    #pragma unroll
    for (int mt = 0; mt < 2; mt++)
        #pragma unroll
        for (int nt = 0; nt < 8; nt++)
            #pragma unroll
            for (int j = 0; j < 4; j++) acc[mt][nt][j] = 0.f;

    float4 wpre[4];
    #pragma unroll
    for (int kc = 0; kc < 4; kc++) {
        if (kc < 3) {   // prefetch next W chunk to regs
            #pragma unroll
            for (int t = 0; t < 4; t++) {
                int f = t * 256 + tid;
                wpre[t] = gW[(f >> 3) * 32 + (kc + 1) * 8 + (f & 7)];
            }
        }
        const float* buf = sW + (kc & 1) * 128 * WS2;
        #pragma unroll
        for (int ks = 0; ks < 4; ks++) {
            const int k = kc * 32 + ks * 8;
            uint32_t afr[2][4];
            #pragma unroll
            for (int mt = 0; mt < 2; mt++) {
                const float* Ap = sX + (wm * 32 + mt * 16 + g) * XS2 + k + tg;
                afr[mt][0] = fu(Ap[0]);
                afr[mt][1] = fu(Ap[8 * XS2]);
                afr[mt][2] = fu(Ap[4]);
                afr[mt][3] = fu(Ap[8 * XS2 + 4]);
            }
            #pragma unroll
            for (int nt = 0; nt < 8; nt++) {
                const float* Bp = buf + (wn * 64 + nt * 8 + g) * WS2 + ks * 8 + tg;
                uint32_t bfr[2] = { fu(Bp[0]), fu(Bp[4]) };
                mma8(acc[0][nt], afr[0], bfr);
                mma8(acc[1][nt], afr[1], bfr);
            }
        }
        if (kc < 3) {
            __syncthreads();     // everyone done reading target buffer
            float* dbuf = sW + ((kc + 1) & 1) * 128 * WS2;
            #pragma unroll
            for (int t = 0; t < 4; t++) {
                int f = t * 256 + tid;
                int n = f >> 3, c4 = f & 7;
                float* d = dbuf + n * WS2 + c4 * 4;
                d[0] = to_tf32(wpre[t].x); d[1] = to_tf32(wpre[t].y);
                d[2] = to_tf32(wpre[t].z); d[3] = to_tf32(wpre[t].w);
            }
            __syncthreads();
        }
    }

    // ---- epilogue: bias, alpha, store fp32 ----
    #pragma unroll
    for (int mt = 0; mt < 2; mt++) {
        const int r0 = mBase + wm * 32 + mt * 16 + g;
        #pragma unroll
        for (int nt = 0; nt < 8; nt++) {
            const int c = wn * 64 + nt * 8 + 2 * tg;
            const float b0 = Bb[c], b1 = Bb[c + 1];
            float2 v0 = make_float2((acc[mt][nt][0] + b0) * alpha,
                                    (acc[mt][nt][1] + b1) * alpha);
            *reinterpret_cast<float2*>(O + r0 * DIM + c) = v0;
            float2 v1 = make_float2((acc[mt][nt][2] + b0) * alpha,
                                    (acc[mt][nt][3] + b1) * alpha);
            *reinterpret_cast<float2*>(O + (r0 + 8) * DIM + c) = v1;
        }
    }
}

// =====================================================================
// Attention: per window (4096 CTAs, 256 thr). q is pre-scaled.
// smem 99KB (q,k,v tiles; P overlays dead q+k) -> 2 CTAs/SM.
// =====================================================================
__device__ __forceinline__ void stage_tile(float* dst, const float* __restrict__ src, int tid) {
    for (int i = tid; i < NTOK * 32; i += 256) {
        int r = i >> 5, c4 = i & 31;
        float4 v = reinterpret_cast<const float4*>(src)[i];
        float* d = dst + r * XS + c4 * 4;
        d[0] = to_tf32(v.x); d[1] = to_tf32(v.y);
        d[2] = to_tf32(v.z); d[3] = to_tf32(v.w);
    }
    for (int i = tid; i < (MPAD - NTOK) * 32; i += 256) {
        int r = NTOK + (i >> 5), c4 = i & 31;
        *reinterpret_cast<float4*>(dst + r * XS + c4 * 4) =
            make_float4(0.f, 0.f, 0.f, 0.f);
    }
}

__global__ __launch_bounds__(256, 2)
void attn_kernel(const float* __restrict__ gq, const float* __restrict__ gk,
                 const float* __restrict__ gv, const float* __restrict__ mask,
                 float* __restrict__ x2)
{
    extern __shared__ float sm[];
    float* sQ = sm;                // 64 x 132
    float* sK = sQ + MPAD * XS;    // 64 x 132
    float* sV = sK + MPAD * XS;    // 64 x 132
    float* sP = sQ;                // overlays Q+K: 4 x 64 x 66 = 16896 floats

    const int tid = threadIdx.x;
    const int warp = tid >> 5, lane = tid & 31;
    const int g = lane >> 2, tg = lane & 3;
    const int b = blockIdx.x;
    const int base = b * NTOK * DIM;

    stage_tile(sQ, gq + base, tid);
    stage_tile(sK, gk + base, tid);
    stage_tile(sV, gv + base, tid);
    __syncthreads();

    const int h = warp >> 1;            // head
    const int mB = (warp & 1) * 32;     // row half

    // ---- S = q @ k^T (q pre-scaled) ----
    float accS[2][8][4];
    #pragma unroll
    for (int mt = 0; mt < 2; mt++)
        #pragma unroll
        for (int nt = 0; nt < 8; nt++)
            #pragma unroll
            for (int j = 0; j < 4; j++) accS[mt][nt][j] = 0.f;

    #pragma unroll
    for (int kk = 0; kk < 4; kk++) {
        const int k = h * HD + kk * 8;
        uint32_t a[2][4];
        #pragma unroll
        for (int mt = 0; mt < 2; mt++) {
            const float* Ap = sQ + (mB + mt * 16 + g) * XS + k + tg;
            a[mt][0] = fu(Ap[0]);
            a[mt][1] = fu(Ap[8 * XS]);
            a[mt][2] = fu(Ap[4]);
            a[mt][3] = fu(Ap[8 * XS + 4]);
        }
        #pragma unroll
        for (int nt = 0; nt < 8; nt++) {
            const float* Bp = sK + (nt * 8 + g) * XS + k + tg;
            uint32_t bfr[2] = { fu(Bp[0]), fu(Bp[4]) };
            mma8(accS[0][nt], a[0], bfr);
            mma8(accS[1][nt], a[1], bfr);
        }
    }
    __syncthreads();   // all warps finished reading sQ/sK -> safe to overlay P

    // ---- bias + mask + softmax, write P into sP ----
    const float* maskp = mask + (b & (NWIN - 1)) * NTOK * NTOK;
    float* Ph = sP + h * MPAD * PS;

    #pragma unroll
    for (int mt = 0; mt < 2; mt++) {
        #pragma unroll
        for (int rs = 0; rs < 2; rs++) {
            const int r = mB + mt * 16 + rs * 8 + g;
            float lv[16];
            #pragma unroll
            for (int nt = 0; nt < 8; nt++) {
                #pragma unroll
                for (int j = 0; j < 2; j++) {
                    const int c = nt * 8 + 2 * tg + j;
                    float l = accS[mt][nt][rs * 2 + j];
                    if (c >= NTOK) l = -1e30f;
                    else if (r < NTOK)
                        l += g_relBias[(h * MPAD + r) * MPAD + c] + maskp[r * NTOK + c];
                    lv[nt * 2 + j] = l;
                }
            }
            float m = lv[0];
            #pragma unroll
            for (int i = 1; i < 16; i++) m = fmaxf(m, lv[i]);
            m = fmaxf(m, __shfl_xor_sync(0xffffffffu, m, 1));
            m = fmaxf(m, __shfl_xor_sync(0xffffffffu, m, 2));
            float s = 0.f;
            #pragma unroll
            for (int i = 0; i < 16; i++) { lv[i] = __expf(lv[i] - m); s += lv[i]; }
            s += __shfl_xor_sync(0xffffffffu, s, 1);
            s += __shfl_xor_sync(0xffffffffu, s, 2);
            const float inv = 1.f / s;
            #pragma unroll
            for (int nt = 0; nt < 8; nt++) {
                float2 v = make_float2(to_tf32(lv[nt * 2] * inv),
                                       to_tf32(lv[nt * 2 + 1] * inv));
                *reinterpret_cast<float2*>(Ph + r * PS + nt * 8 + 2 * tg) = v;
            }
        }
    }
    __syncthreads();

    // ---- O = P @ V_h, write x2 directly ----
    float accO[2][4][4];
    #pragma unroll
    for (int mt = 0; mt < 2; mt++)
        #pragma unroll
        for (int nt = 0; nt < 4; nt++)
            #pragma unroll
            for (int j = 0; j < 4; j++) accO[mt][nt][j] = 0.f;

    #pragma unroll
    for (int kk = 0; kk < 8; kk++) {
        const int k = kk * 8;
        uint32_t a[2][4];
        #pragma unroll
        for (int mt = 0; mt < 2; mt++) {
            const float* Ap = Ph + (mB + mt * 16 + g) * PS + k + tg;
            a[mt][0] = fu(Ap[0]);
            a[mt][1] = fu(Ap[8 * PS]);
            a[mt][2] = fu(Ap[4]);
            a[mt][3] = fu(Ap[8 * PS + 4]);
        }
        #pragma unroll
        for (int nt = 0; nt < 4; nt++) {
            const float* Bp = sV + (k + tg) * XS + h * HD + nt * 8 + g;
            uint32_t bfr[2] = { fu(Bp[0]), fu(Bp[4 * XS]) };
            mma8(accO[0][nt], a[0], bfr);
            mma8(accO[1][nt], a[1], bfr);
        }
    }

    float* xo = x2 + base;
    #pragma unroll
    for (int mt = 0; mt < 2; mt++) {
        #pragma unroll
        for (int nt = 0; nt < 4; nt++) {
            const int c = h * HD + nt * 8 + 2 * tg;
            const int r0 = mB + mt * 16 + g, r1 = r0 + 8;
            if (r0 < NTOK)
                *reinterpret_cast<float2*>(xo + r0 * DIM + c) =
                    make_float2(accO[mt][nt][0], accO[mt][nt][1]);
            if (r1 < NTOK)
                *reinterpret_cast<float2*>(xo + r1 * DIM + c) =
                    make_float2(accO[mt][nt][2], accO[mt][nt][3]);
        }
    }
}

#define PROJ_SMEM ((128 * XS2 + 2 * 128 * WS2) * 4)
#define ATTN_SMEM ((3 * MPAD * XS) * 4)
#define QSCALE 0.17677669529663687f

extern "C" void kernel_launch(void* const* d_in, const int* in_sizes, int n_in,
                              void* d_out, int out_size)
{
    const float* query      = (const float*)d_in[0];
    const float* key        = (const float*)d_in[1];
    const float* value      = (const float*)d_in[2];
    const float* Wq         = (const float*)d_in[3];
    const float* bq         = (const float*)d_in[4];
    const float* Wk         = (const float*)d_in[5];
    const float* bk         = (const float*)d_in[6];
    const float* Wv         = (const float*)d_in[7];
    const float* bv         = (const float*)d_in[8];
    const float* bias_table = (const float*)d_in[9];
    const float* Wp         = (const float*)d_in[10];
    const float* bp         = (const float*)d_in[11];
    const float* mask       = (const float*)d_in[12];
    const int*   rel_index  = (const int*)d_in[13];
    float* out = (float*)d_out;

    float* q = nullptr; float* k = nullptr; float* v = nullptr; float* x2 = nullptr;
    cudaGetSymbolAddress((void**)&q,  g_q);
    cudaGetSymbolAddress((void**)&k,  g_k);
    cudaGetSymbolAddress((void**)&v,  g_v);
    cudaGetSymbolAddress((void**)&x2, g_x2);

    cudaFuncSetAttribute(proj_kernel,
                         cudaFuncAttributeMaxDynamicSharedMemorySize, PROJ_SMEM);
    cudaFuncSetAttribute(attn_kernel,
                         cudaFuncAttributeMaxDynamicSharedMemorySize, ATTN_SMEM);

    relbias_kernel<<<(HEADS * MPAD * MPAD + 255) / 256, 256>>>(bias_table, rel_index);

    proj_kernel<<<dim3(NROWS / 128, 3), 256, PROJ_SMEM>>>(
        query, key, value, Wq, Wk, Wv, bq, bk, bv, q, k, v,
        QSCALE, 1.f, 1.f);

    attn_kernel<<<NBLK, 256, ATTN_SMEM>>>(q, k, v, mask, x2);

    proj_kernel<<<dim3(NROWS / 128, 1), 256, PROJ_SMEM>>>(
        x2, x2, x2, Wp, Wp, Wp, bp, bp, bp, out, out, out,
        1.f, 1.f, 1.f);
}

// round 5
// speedup vs baseline: 1.8245x; 1.0113x over previous
#include <cuda_runtime.h>
#include <cstdint>

#define NTOK 49
#define MPAD 64
#define DIM 128
#define HEADS 4
#define HD 32
#define NWIN 64
#define NBLK 4096
#define NROWS (NBLK * NTOK)          // 200704
#define XS 132   // padded stride for 64x128 attn tiles
#define XS2 132  // proj input tile stride
#define WS2 36   // proj weight k-chunk stride (32 + 4 pad)

// ---------------- global scratch (allocation-free) ----------------
__device__ float g_q[NROWS * DIM];
__device__ float g_k[NROWS * DIM];
__device__ float g_v[NROWS * DIM];
__device__ float g_x2[NROWS * DIM];
__device__ float g_relBias[HEADS * MPAD * MPAD];

__global__ void relbias_kernel(const float* __restrict__ bias_table,
                               const int* __restrict__ rel_index)
{
    int idx = blockIdx.x * blockDim.x + threadIdx.x;
    if (idx >= HEADS * MPAD * MPAD) return;
    int c = idx & (MPAD - 1);
    int r = (idx >> 6) & (MPAD - 1);
    int h = idx >> 12;
    float v = 0.f;
    if (r < NTOK && c < NTOK)
        v = bias_table[rel_index[r * NTOK + c] * HEADS + h];
    g_relBias[idx] = v;
}

__device__ __forceinline__ float to_tf32(float x) {
    asm("cvt.rna.tf32.f32 %0, %0;" : "+f"(x));
    return x;
}
__device__ __forceinline__ uint32_t fu(float x) { return __float_as_uint(x); }

__device__ __forceinline__ void mma8(float c[4], const uint32_t a[4], const uint32_t b[2]) {
    asm volatile(
        "mma.sync.aligned.m16n8k8.row.col.f32.tf32.tf32.f32 "
        "{%0,%1,%2,%3}, {%4,%5,%6,%7}, {%8,%9}, {%0,%1,%2,%3};\n"
        : "+f"(c[0]), "+f"(c[1]), "+f"(c[2]), "+f"(c[3])
        : "r"(a[0]), "r"(a[1]), "r"(a[2]), "r"(a[3]), "r"(b[0]), "r"(b[1]));
}

// =====================================================================
// Projection GEMM: O[m, n] = (X[m, :] @ W[n, :] + bias[n]) * alpha
// M = 200704, N = K = 128. Grid (1568, nz). M-tile 128. 256 threads.
// smem: X tile 128x132, W double-buffered k-chunks 2 x 128x36. 2 CTAs/SM.
// =====================================================================
__global__ __launch_bounds__(256, 2)
void proj_kernel(const float* __restrict__ X0, const float* __restrict__ X1,
                 const float* __restrict__ X2,
                 const float* __restrict__ W0_, const float* __restrict__ W1_,
                 const float* __restrict__ W2_,
                 const float* __restrict__ B0_, const float* __restrict__ B1_,
                 const float* __restrict__ B2_,
                 float* __restrict__ O0_, float* __restrict__ O1_,
                 float* __restrict__ O2_,
                 float a0, float a1, float a2)
{
    extern __shared__ float sm[];
    float* sX = sm;                   // 128 x 132
    float* sW = sX + 128 * XS2;       // 2 x 128 x 36

    const float* X; const float* W; const float* Bb; float* O; float alpha;
    if (blockIdx.y == 0)      { X = X0; W = W0_; Bb = B0_; O = O0_; alpha = a0; }
    else if (blockIdx.y == 1) { X = X1; W = W1_; Bb = B1_; O = O1_; alpha = a1; }
    else                      { X = X2; W = W2_; Bb = B2_; O = O2_; alpha = a2; }

    const int tid  = threadIdx.x;
    const int warp = tid >> 5, lane = tid & 31;
    const int g = lane >> 2, tg = lane & 3;
    const int mBase = blockIdx.x * 128;

    // ---- stage X tile (tf32-rounded) ----
    const float4* gX = reinterpret_cast<const float4*>(X + mBase * DIM);
    #pragma unroll
    for (int t = 0; t < 16; t++) {
        int f = t * 256 + tid;
        int r = f >> 5, c4 = f & 31;
        float4 v = gX[f];
        float* d = sX + r * XS2 + c4 * 4;
        d[0] = to_tf32(v.x); d[1] = to_tf32(v.y);
        d[2] = to_tf32(v.z); d[3] = to_tf32(v.w);
    }
    // ---- W chunk 0 -> buffer 0 ----
    const float4* gW = reinterpret_cast<const float4*>(W);
    #pragma unroll
    for (int t = 0; t < 4; t++) {
        int f = t * 256 + tid;
        int n = f >> 3, c4 = f & 7;
        float4 v = gW[n * 32 + c4];                 // chunk 0: cols 0..31
        float* d = sW + n * WS2 + c4 * 4;
        d[0] = to_tf32(v.x); d[1] = to_tf32(v.y);
        d[2] = to_tf32(v.z); d[3] = to_tf32(v.w);
    }
    __syncthreads();

    const int wm = warp & 3;     // 4 m-chunks of 32 rows
    const int wn = warp >> 2;    // 2 n-chunks of 64 cols
    float acc[2][8][4];
    #pragma unroll
    for (int mt = 0; mt < 2; mt++)
        #pragma unroll
        for (int nt = 0; nt < 8; nt++)
            #pragma unroll
            for (int j = 0; j < 4; j++) acc[mt][nt][j] = 0.f;

    float4 wpre[4];
    #pragma unroll
    for (int kc = 0; kc < 4; kc++) {
        if (kc < 3) {   // prefetch next W chunk to regs
            #pragma unroll
            for (int t = 0; t < 4; t++) {
                int f = t * 256 + tid;
                wpre[t] = gW[(f >> 3) * 32 + (kc + 1) * 8 + (f & 7)];
            }
        }
        const float* buf = sW + (kc & 1) * 128 * WS2;
        #pragma unroll
        for (int ks = 0; ks < 4; ks++) {
            const int k = kc * 32 + ks * 8;
            uint32_t afr[2][4];
            #pragma unroll
            for (int mt = 0; mt < 2; mt++) {
                const float* Ap = sX + (wm * 32 + mt * 16 + g) * XS2 + k + tg;
                afr[mt][0] = fu(Ap[0]);
                afr[mt][1] = fu(Ap[8 * XS2]);
                afr[mt][2] = fu(Ap[4]);
                afr[mt][3] = fu(Ap[8 * XS2 + 4]);
            }
            #pragma unroll
            for (int nt = 0; nt < 8; nt++) {
                const float* Bp = buf + (wn * 64 + nt * 8 + g) * WS2 + ks * 8 + tg;
                uint32_t bfr[2] = { fu(Bp[0]), fu(Bp[4]) };
                mma8(acc[0][nt], afr[0], bfr);
                mma8(acc[1][nt], afr[1], bfr);
            }
        }
        if (kc < 3) {
            __syncthreads();     // everyone done reading target buffer
            float* dbuf = sW + ((kc + 1) & 1) * 128 * WS2;
            #pragma unroll
            for (int t = 0; t < 4; t++) {
                int f = t * 256 + tid;
                int n = f >> 3, c4 = f & 7;
                float* d = dbuf + n * WS2 + c4 * 4;
                d[0] = to_tf32(wpre[t].x); d[1] = to_tf32(wpre[t].y);
                d[2] = to_tf32(wpre[t].z); d[3] = to_tf32(wpre[t].w);
            }
            __syncthreads();
        }
    }

    // ---- epilogue: bias, alpha, store fp32 ----
    #pragma unroll
    for (int mt = 0; mt < 2; mt++) {
        const int r0 = mBase + wm * 32 + mt * 16 + g;
        #pragma unroll
        for (int nt = 0; nt < 8; nt++) {
            const int c = wn * 64 + nt * 8 + 2 * tg;
            const float b0 = Bb[c], b1 = Bb[c + 1];
            float2 v0 = make_float2((acc[mt][nt][0] + b0) * alpha,
                                    (acc[mt][nt][1] + b1) * alpha);
            *reinterpret_cast<float2*>(O + r0 * DIM + c) = v0;
            float2 v1 = make_float2((acc[mt][nt][2] + b0) * alpha,
                                    (acc[mt][nt][3] + b1) * alpha);
            *reinterpret_cast<float2*>(O + (r0 + 8) * DIM + c) = v1;
        }
    }
}

// =====================================================================
// Attention: per window (4096 CTAs, 256 thr). q is pre-scaled.
// 8 warps x 2 sequential tasks = 16 tasks (4 heads x 4 row-groups of 16).
// S kept in registers; softmax in-register; C->A fragment permutation via
// intra-quad shuffles (no P smem, no inter-task syncs). Regs fit 128.
// smem 102KB (q,k,v tiles) -> 2 CTAs/SM.
// =====================================================================
__device__ __forceinline__ void stage_tile(float* dst, const float* __restrict__ src, int tid) {
    for (int i = tid; i < NTOK * 32; i += 256) {
        int r = i >> 5, c4 = i & 31;
        float4 v = reinterpret_cast<const float4*>(src)[i];
        float* d = dst + r * XS + c4 * 4;
        d[0] = to_tf32(v.x); d[1] = to_tf32(v.y);
        d[2] = to_tf32(v.z); d[3] = to_tf32(v.w);
    }
    for (int i = tid; i < (MPAD - NTOK) * 32; i += 256) {
        int r = NTOK + (i >> 5), c4 = i & 31;
        *reinterpret_cast<float4*>(dst + r * XS + c4 * 4) =
            make_float4(0.f, 0.f, 0.f, 0.f);
    }
}

__global__ __launch_bounds__(256, 2)
void attn_kernel(const float* __restrict__ gq, const float* __restrict__ gk,
                 const float* __restrict__ gv, const float* __restrict__ mask,
                 float* __restrict__ x2)
{
    extern __shared__ float sm[];
    float* sQ = sm;                // 64 x 132
    float* sK = sQ + MPAD * XS;    // 64 x 132
    float* sV = sK + MPAD * XS;    // 64 x 132

    const int tid = threadIdx.x;
    const int warp = tid >> 5, lane = tid & 31;
    const int g = lane >> 2, tg = lane & 3;
    const int b = blockIdx.x;
    const int base = b * NTOK * DIM;

    stage_tile(sQ, gq + base, tid);
    stage_tile(sK, gk + base, tid);
    stage_tile(sV, gv + base, tid);
    __syncthreads();

    const float* maskp = mask + (b & (NWIN - 1)) * NTOK * NTOK;
    float* xo = x2 + base;

    // quad-shuffle source lanes for C->A fragment permutation
    const int sl0 = (lane & ~3) | (tg >> 1);   // cols tg
    const int sl1 = sl0 + 2;                   // cols tg+4

    #pragma unroll
    for (int task = 0; task < 2; task++) {
        const int rg = task * 8 + warp;        // 0..15
        const int h  = rg >> 2;                // head
        const int mB = (rg & 3) * 16;          // 16-row group

        // ---- S = q_h @ k_h^T, 16x64 per warp (q pre-scaled) ----
        float acc[8][4];
        #pragma unroll
        for (int nt = 0; nt < 8; nt++)
            #pragma unroll
            for (int j = 0; j < 4; j++) acc[nt][j] = 0.f;

        #pragma unroll
        for (int kk = 0; kk < 4; kk++) {
            const int k = h * HD + kk * 8;
            uint32_t a[4];
            const float* Ap = sQ + (mB + g) * XS + k + tg;
            a[0] = fu(Ap[0]);
            a[1] = fu(Ap[8 * XS]);
            a[2] = fu(Ap[4]);
            a[3] = fu(Ap[8 * XS + 4]);
            #pragma unroll
            for (int nt = 0; nt < 8; nt++) {
                const float* Bp = sK + (nt * 8 + g) * XS + k + tg;
                uint32_t bfr[2] = { fu(Bp[0]), fu(Bp[4]) };
                mma8(acc[nt], a, bfr);
            }
        }

        // ---- bias + mask + softmax, in-register; acc becomes P ----
        #pragma unroll
        for (int rs = 0; rs < 2; rs++) {
            const int r = mB + rs * 8 + g;
            float lv[16];
            #pragma unroll
            for (int nt = 0; nt < 8; nt++) {
                #pragma unroll
                for (int j = 0; j < 2; j++) {
                    const int c = nt * 8 + 2 * tg + j;
                    float l = acc[nt][rs * 2 + j];
                    if (c >= NTOK) l = -1e30f;
                    else if (r < NTOK)
                        l += g_relBias[(h * MPAD + r) * MPAD + c] + maskp[r * NTOK + c];
                    lv[nt * 2 + j] = l;
                }
            }
            float m = lv[0];
            #pragma unroll
            for (int i = 1; i < 16; i++) m = fmaxf(m, lv[i]);
            m = fmaxf(m, __shfl_xor_sync(0xffffffffu, m, 1));
            m = fmaxf(m, __shfl_xor_sync(0xffffffffu, m, 2));
            float s = 0.f;
            #pragma unroll
            for (int i = 0; i < 16; i++) { lv[i] = __expf(lv[i] - m); s += lv[i]; }
            s += __shfl_xor_sync(0xffffffffu, s, 1);
            s += __shfl_xor_sync(0xffffffffu, s, 2);
            const float inv = 1.f / s;
            #pragma unroll
            for (int nt = 0; nt < 8; nt++) {
                acc[nt][rs * 2 + 0] = to_tf32(lv[nt * 2 + 0] * inv);
                acc[nt][rs * 2 + 1] = to_tf32(lv[nt * 2 + 1] * inv);
            }
        }

        // ---- O = P @ V_h: 16x32 per warp; A-fragments via quad shfl ----
        float accO[4][4];
        #pragma unroll
        for (int nt = 0; nt < 4; nt++)
            #pragma unroll
            for (int j = 0; j < 4; j++) accO[nt][j] = 0.f;

        #pragma unroll
        for (int kk = 0; kk < 8; kk++) {
            // C-fragment acc[kk] holds P[rows {mB+g, mB+8+g}][cols kk*8 + {2tg,2tg+1}]
            // A-fragment needs  P[rows {.., ..}][cols kk*8 + {tg, tg+4}]
            float x0 = __shfl_sync(0xffffffffu, acc[kk][0], sl0);
            float x1 = __shfl_sync(0xffffffffu, acc[kk][1], sl0);
            float x2v = __shfl_sync(0xffffffffu, acc[kk][2], sl0);
            float x3 = __shfl_sync(0xffffffffu, acc[kk][3], sl0);
            float y0 = __shfl_sync(0xffffffffu, acc[kk][0], sl1);
            float y1 = __shfl_sync(0xffffffffu, acc[kk][1], sl1);
            float y2 = __shfl_sync(0xffffffffu, acc[kk][2], sl1);
            float y3 = __shfl_sync(0xffffffffu, acc[kk][3], sl1);
            uint32_t a[4];
            a[0] = fu((tg & 1) ? x1 : x0);
            a[1] = fu((tg & 1) ? x3 : x2v);
            a[2] = fu((tg & 1) ? y1 : y0);
            a[3] = fu((tg & 1) ? y3 : y2);
            #pragma unroll
            for (int nt = 0; nt < 4; nt++) {
                const float* Bp = sV + (kk * 8 + tg) * XS + h * HD + nt * 8 + g;
                uint32_t bfr[2] = { fu(Bp[0]), fu(Bp[4 * XS]) };
                mma8(accO[nt], a, bfr);
            }
        }

        // ---- store O rows (16 x 32 slice) ----
        const int r0 = mB + g, r1 = r0 + 8;
        #pragma unroll
        for (int nt = 0; nt < 4; nt++) {
            const int c = h * HD + nt * 8 + 2 * tg;
            if (r0 < NTOK)
                *reinterpret_cast<float2*>(xo + r0 * DIM + c) =
                    make_float2(accO[nt][0], accO[nt][1]);
            if (r1 < NTOK)
                *reinterpret_cast<float2*>(xo + r1 * DIM + c) =
                    make_float2(accO[nt][2], accO[nt][3]);
        }
    }
}

#define PROJ_SMEM ((128 * XS2 + 2 * 128 * WS2) * 4)
#define ATTN_SMEM ((3 * MPAD * XS) * 4)
#define QSCALE 0.17677669529663687f

extern "C" void kernel_launch(void* const* d_in, const int* in_sizes, int n_in,
                              void* d_out, int out_size)
{
    const float* query      = (const float*)d_in[0];
    const float* key        = (const float*)d_in[1];
    const float* value      = (const float*)d_in[2];
    const float* Wq         = (const float*)d_in[3];
    const float* bq         = (const float*)d_in[4];
    const float* Wk         = (const float*)d_in[5];
    const float* bk         = (const float*)d_in[6];
    const float* Wv         = (const float*)d_in[7];
    const float* bv         = (const float*)d_in[8];
    const float* bias_table = (const float*)d_in[9];
    const float* Wp         = (const float*)d_in[10];
    const float* bp         = (const float*)d_in[11];
    const float* mask       = (const float*)d_in[12];
    const int*   rel_index  = (const int*)d_in[13];
    float* out = (float*)d_out;

    float* q = nullptr; float* k = nullptr; float* v = nullptr; float* x2 = nullptr;
    cudaGetSymbolAddress((void**)&q,  g_q);
    cudaGetSymbolAddress((void**)&k,  g_k);
    cudaGetSymbolAddress((void**)&v,  g_v);
    cudaGetSymbolAddress((void**)&x2, g_x2);

    cudaFuncSetAttribute(proj_kernel,
                         cudaFuncAttributeMaxDynamicSharedMemorySize, PROJ_SMEM);
    cudaFuncSetAttribute(attn_kernel,
                         cudaFuncAttributeMaxDynamicSharedMemorySize, ATTN_SMEM);

    relbias_kernel<<<(HEADS * MPAD * MPAD + 255) / 256, 256>>>(bias_table, rel_index);

    proj_kernel<<<dim3(NROWS / 128, 3), 256, PROJ_SMEM>>>(
        query, key, value, Wq, Wk, Wv, bq, bk, bv, q, k, v,
        QSCALE, 1.f, 1.f);

    attn_kernel<<<NBLK, 256, ATTN_SMEM>>>(q, k, v, mask, x2);

    proj_kernel<<<dim3(NROWS / 128, 1), 256, PROJ_SMEM>>>(
        x2, x2, x2, Wp, Wp, Wp, bp, bp, bp, out, out, out,
        1.f, 1.f, 1.f);
}

// round 6
// speedup vs baseline: 1.9405x; 1.0636x over previous
#include <cuda_runtime.h>
#include <cstdint>

#define NTOK 49
#define MPAD 64
#define DIM 128
#define HEADS 4
#define HD 32
#define NWIN 64
#define NBLK 4096
#define NROWS (NBLK * NTOK)          // 200704
#define XS 132   // padded stride for 64x128 attn tiles
#define XS2 132  // proj input tile stride
#define WS2 36   // proj weight k-chunk stride (32 + 4 pad)

// ---------------- global scratch (allocation-free) ----------------
__device__ float g_q[NROWS * DIM];
__device__ float g_k[NROWS * DIM];
__device__ float g_v[NROWS * DIM];
__device__ float g_x2[NROWS * DIM];
// fused (relbias + mask) in mma C-fragment layout:
// [win][h][mg][rs][nt][lane] float2
__device__ float2 g_biasF[NWIN * HEADS * 4 * 2 * 8 * 32];

__global__ void biasfrag_kernel(const float* __restrict__ bias_table,
                                const int* __restrict__ rel_index,
                                const float* __restrict__ mask)
{
    int idx = blockIdx.x * 256 + threadIdx.x;   // 2,097,152 total, exact grid
    int lane = idx & 31;
    int nt   = (idx >> 5) & 7;
    int rs   = (idx >> 8) & 1;
    int mg   = (idx >> 9) & 3;
    int h    = (idx >> 11) & 3;
    int win  = idx >> 13;                       // < 64
    int g = lane >> 2, tg = lane & 3;
    int r = mg * 16 + rs * 8 + g;
    int c0 = nt * 8 + 2 * tg;

    float2 v;
    // j = 0
    if (c0 >= NTOK)      v.x = -1e30f;
    else if (r >= NTOK)  v.x = 0.f;
    else v.x = bias_table[rel_index[r * NTOK + c0] * HEADS + h]
             + mask[(win * NTOK + r) * NTOK + c0];
    // j = 1
    int c1 = c0 + 1;
    if (c1 >= NTOK)      v.y = -1e30f;
    else if (r >= NTOK)  v.y = 0.f;
    else v.y = bias_table[rel_index[r * NTOK + c1] * HEADS + h]
             + mask[(win * NTOK + r) * NTOK + c1];

    g_biasF[idx] = v;
}

__device__ __forceinline__ float to_tf32(float x) {
    asm("cvt.rna.tf32.f32 %0, %0;" : "+f"(x));
    return x;
}
__device__ __forceinline__ uint32_t fu(float x) { return __float_as_uint(x); }

__device__ __forceinline__ void mma8(float c[4], const uint32_t a[4], const uint32_t b[2]) {
    asm volatile(
        "mma.sync.aligned.m16n8k8.row.col.f32.tf32.tf32.f32 "
        "{%0,%1,%2,%3}, {%4,%5,%6,%7}, {%8,%9}, {%0,%1,%2,%3};\n"
        : "+f"(c[0]), "+f"(c[1]), "+f"(c[2]), "+f"(c[3])
        : "r"(a[0]), "r"(a[1]), "r"(a[2]), "r"(a[3]), "r"(b[0]), "r"(b[1]));
}

// =====================================================================
// Projection GEMM: O[m, n] = (X[m, :] @ W[n, :] + bias[n]) * alpha
// M = 200704, N = K = 128. Grid (1568, nz). M-tile 128. 256 threads.
// smem: X tile 128x132, W double-buffered k-chunks 2 x 128x36. 2 CTAs/SM.
// =====================================================================
__global__ __launch_bounds__(256, 2)
void proj_kernel(const float* __restrict__ X0, const float* __restrict__ X1,
                 const float* __restrict__ X2,
                 const float* __restrict__ W0_, const float* __restrict__ W1_,
                 const float* __restrict__ W2_,
                 const float* __restrict__ B0_, const float* __restrict__ B1_,
                 const float* __restrict__ B2_,
                 float* __restrict__ O0_, float* __restrict__ O1_,
                 float* __restrict__ O2_,
                 float a0, float a1, float a2)
{
    extern __shared__ float sm[];
    float* sX = sm;                   // 128 x 132
    float* sW = sX + 128 * XS2;       // 2 x 128 x 36

    const float* X; const float* W; const float* Bb; float* O; float alpha;
    if (blockIdx.y == 0)      { X = X0; W = W0_; Bb = B0_; O = O0_; alpha = a0; }
    else if (blockIdx.y == 1) { X = X1; W = W1_; Bb = B1_; O = O1_; alpha = a1; }
    else                      { X = X2; W = W2_; Bb = B2_; O = O2_; alpha = a2; }

    const int tid  = threadIdx.x;
    const int warp = tid >> 5, lane = tid & 31;
    const int g = lane >> 2, tg = lane & 3;
    const int mBase = blockIdx.x * 128;

    // ---- stage X tile (tf32-rounded) ----
    const float4* gX = reinterpret_cast<const float4*>(X + mBase * DIM);
    #pragma unroll
    for (int t = 0; t < 16; t++) {
        int f = t * 256 + tid;
        int r = f >> 5, c4 = f & 31;
        float4 v = gX[f];
        v.x = to_tf32(v.x); v.y = to_tf32(v.y);
        v.z = to_tf32(v.z); v.w = to_tf32(v.w);
        *reinterpret_cast<float4*>(sX + r * XS2 + c4 * 4) = v;
    }
    // ---- W chunk 0 -> buffer 0 ----
    const float4* gW = reinterpret_cast<const float4*>(W);
    #pragma unroll
    for (int t = 0; t < 4; t++) {
        int f = t * 256 + tid;
        int n = f >> 3, c4 = f & 7;
        float4 v = gW[n * 32 + c4];                 // chunk 0: cols 0..31
        v.x = to_tf32(v.x); v.y = to_tf32(v.y);
        v.z = to_tf32(v.z); v.w = to_tf32(v.w);
        *reinterpret_cast<float4*>(sW + n * WS2 + c4 * 4) = v;
    }
    __syncthreads();

    const int wm = warp & 3;     // 4 m-chunks of 32 rows
    const int wn = warp >> 2;    // 2 n-chunks of 64 cols
    float acc[2][8][4];
    #pragma unroll
    for (int mt = 0; mt < 2; mt++)
        #pragma unroll
        for (int nt = 0; nt < 8; nt++)
            #pragma unroll
            for (int j = 0; j < 4; j++) acc[mt][nt][j] = 0.f;

    float4 wpre[4];
    #pragma unroll
    for (int kc = 0; kc < 4; kc++) {
        if (kc < 3) {   // prefetch next W chunk to regs
            #pragma unroll
            for (int t = 0; t < 4; t++) {
                int f = t * 256 + tid;
                wpre[t] = gW[(f >> 3) * 32 + (kc + 1) * 8 + (f & 7)];
            }
        }
        const float* buf = sW + (kc & 1) * 128 * WS2;
        #pragma unroll
        for (int ks = 0; ks < 4; ks++) {
            const int k = kc * 32 + ks * 8;
            uint32_t afr[2][4];
            #pragma unroll
            for (int mt = 0; mt < 2; mt++) {
                const float* Ap = sX + (wm * 32 + mt * 16 + g) * XS2 + k + tg;
                afr[mt][0] = fu(Ap[0]);
                afr[mt][1] = fu(Ap[8 * XS2]);
                afr[mt][2] = fu(Ap[4]);
                afr[mt][3] = fu(Ap[8 * XS2 + 4]);
            }
            #pragma unroll
            for (int nt = 0; nt < 8; nt++) {
                const float* Bp = buf + (wn * 64 + nt * 8 + g) * WS2 + ks * 8 + tg;
                uint32_t bfr[2] = { fu(Bp[0]), fu(Bp[4]) };
                mma8(acc[0][nt], afr[0], bfr);
                mma8(acc[1][nt], afr[1], bfr);
            }
        }
        if (kc < 3) {
            __syncthreads();     // everyone done reading target buffer
            float* dbuf = sW + ((kc + 1) & 1) * 128 * WS2;
            #pragma unroll
            for (int t = 0; t < 4; t++) {
                int f = t * 256 + tid;
                int n = f >> 3, c4 = f & 7;
                float4 v = wpre[t];
                v.x = to_tf32(v.x); v.y = to_tf32(v.y);
                v.z = to_tf32(v.z); v.w = to_tf32(v.w);
                *reinterpret_cast<float4*>(dbuf + n * WS2 + c4 * 4) = v;
            }
            __syncthreads();
        }
    }

    // ---- epilogue: bias, alpha, store fp32 ----
    #pragma unroll
    for (int mt = 0; mt < 2; mt++) {
        const int r0 = mBase + wm * 32 + mt * 16 + g;
        #pragma unroll
        for (int nt = 0; nt < 8; nt++) {
            const int c = wn * 64 + nt * 8 + 2 * tg;
            const float b0 = Bb[c], b1 = Bb[c + 1];
            float2 v0 = make_float2((acc[mt][nt][0] + b0) * alpha,
                                    (acc[mt][nt][1] + b1) * alpha);
            *reinterpret_cast<float2*>(O + r0 * DIM + c) = v0;
            float2 v1 = make_float2((acc[mt][nt][2] + b0) * alpha,
                                    (acc[mt][nt][3] + b1) * alpha);
            *reinterpret_cast<float2*>(O + (r0 + 8) * DIM + c) = v1;
        }
    }
}

// =====================================================================
// Attention: per window (4096 CTAs, 256 thr). q is pre-scaled.
// 8 warps x 2 sequential tasks = 16 tasks (4 heads x 4 row-groups of 16).
// S in registers; bias+mask fetched as 16 coalesced LDG.64 from g_biasF
// (prefetched before QK mma); softmax in-register; C->A fragment
// permutation via intra-quad shuffles. smem 99KB -> 2 CTAs/SM.
// =====================================================================
__device__ __forceinline__ void stage_tile(float* dst, const float* __restrict__ src, int tid) {
    for (int i = tid; i < NTOK * 32; i += 256) {
        int r = i >> 5, c4 = i & 31;
        float4 v = reinterpret_cast<const float4*>(src)[i];
        v.x = to_tf32(v.x); v.y = to_tf32(v.y);
        v.z = to_tf32(v.z); v.w = to_tf32(v.w);
        *reinterpret_cast<float4*>(dst + r * XS + c4 * 4) = v;
    }
    for (int i = tid; i < (MPAD - NTOK) * 32; i += 256) {
        int r = NTOK + (i >> 5), c4 = i & 31;
        *reinterpret_cast<float4*>(dst + r * XS + c4 * 4) =
            make_float4(0.f, 0.f, 0.f, 0.f);
    }
}

__global__ __launch_bounds__(256, 2)
void attn_kernel(const float* __restrict__ gq, const float* __restrict__ gk,
                 const float* __restrict__ gv, float* __restrict__ x2)
{
    extern __shared__ float sm[];
    float* sQ = sm;                // 64 x 132
    float* sK = sQ + MPAD * XS;    // 64 x 132
    float* sV = sK + MPAD * XS;    // 64 x 132

    const int tid = threadIdx.x;
    const int warp = tid >> 5, lane = tid & 31;
    const int g = lane >> 2, tg = lane & 3;
    const int b = blockIdx.x;
    const int base = b * NTOK * DIM;

    stage_tile(sQ, gq + base, tid);
    stage_tile(sK, gk + base, tid);
    stage_tile(sV, gv + base, tid);
    __syncthreads();

    float* xo = x2 + base;
    const float2* bwin = g_biasF + (size_t)(b & (NWIN - 1)) * (HEADS * 4 * 2 * 8 * 32);

    // quad-shuffle source lanes for C->A fragment permutation
    const int sl0 = (lane & ~3) | (tg >> 1);   // cols tg
    const int sl1 = sl0 + 2;                   // cols tg+4

    #pragma unroll
    for (int task = 0; task < 2; task++) {
        const int rg = task * 8 + warp;        // 0..15
        const int h  = rg >> 2;                // head
        const int mg = rg & 3;                 // 16-row group
        const int mB = mg * 16;

        // ---- prefetch fused bias fragments (coalesced LDG.64) ----
        const float2* bfp = bwin + ((h * 4 + mg) * 2 * 8) * 32 + lane;
        float2 bR[2][8];
        #pragma unroll
        for (int rs = 0; rs < 2; rs++)
            #pragma unroll
            for (int nt = 0; nt < 8; nt++)
                bR[rs][nt] = bfp[(rs * 8 + nt) * 32];

        // ---- S = q_h @ k_h^T, 16x64 per warp (q pre-scaled) ----
        float acc[8][4];
        #pragma unroll
        for (int nt = 0; nt < 8; nt++)
            #pragma unroll
            for (int j = 0; j < 4; j++) acc[nt][j] = 0.f;

        #pragma unroll
        for (int kk = 0; kk < 4; kk++) {
            const int k = h * HD + kk * 8;
            uint32_t a[4];
            const float* Ap = sQ + (mB + g) * XS + k + tg;
            a[0] = fu(Ap[0]);
            a[1] = fu(Ap[8 * XS]);
            a[2] = fu(Ap[4]);
            a[3] = fu(Ap[8 * XS + 4]);
            #pragma unroll
            for (int nt = 0; nt < 8; nt++) {
                const float* Bp = sK + (nt * 8 + g) * XS + k + tg;
                uint32_t bfr[2] = { fu(Bp[0]), fu(Bp[4]) };
                mma8(acc[nt], a, bfr);
            }
        }

        // ---- bias + softmax, in-register; acc becomes P ----
        #pragma unroll
        for (int rs = 0; rs < 2; rs++) {
            float lv[16];
            #pragma unroll
            for (int nt = 0; nt < 8; nt++) {
                lv[nt * 2 + 0] = acc[nt][rs * 2 + 0] + bR[rs][nt].x;
                lv[nt * 2 + 1] = acc[nt][rs * 2 + 1] + bR[rs][nt].y;
            }
            float m = lv[0];
            #pragma unroll
            for (int i = 1; i < 16; i++) m = fmaxf(m, lv[i]);
            m = fmaxf(m, __shfl_xor_sync(0xffffffffu, m, 1));
            m = fmaxf(m, __shfl_xor_sync(0xffffffffu, m, 2));
            float s = 0.f;
            #pragma unroll
            for (int i = 0; i < 16; i++) { lv[i] = __expf(lv[i] - m); s += lv[i]; }
            s += __shfl_xor_sync(0xffffffffu, s, 1);
            s += __shfl_xor_sync(0xffffffffu, s, 2);
            const float inv = 1.f / s;
            #pragma unroll
            for (int nt = 0; nt < 8; nt++) {
                acc[nt][rs * 2 + 0] = to_tf32(lv[nt * 2 + 0] * inv);
                acc[nt][rs * 2 + 1] = to_tf32(lv[nt * 2 + 1] * inv);
            }
        }

        // ---- O = P @ V_h: 16x32 per warp; A-fragments via quad shfl ----
        float accO[4][4];
        #pragma unroll
        for (int nt = 0; nt < 4; nt++)
            #pragma unroll
            for (int j = 0; j < 4; j++) accO[nt][j] = 0.f;

        #pragma unroll
        for (int kk = 0; kk < 8; kk++) {
            float x0 = __shfl_sync(0xffffffffu, acc[kk][0], sl0);
            float x1 = __shfl_sync(0xffffffffu, acc[kk][1], sl0);
            float x2v = __shfl_sync(0xffffffffu, acc[kk][2], sl0);
            float x3 = __shfl_sync(0xffffffffu, acc[kk][3], sl0);
            float y0 = __shfl_sync(0xffffffffu, acc[kk][0], sl1);
            float y1 = __shfl_sync(0xffffffffu, acc[kk][1], sl1);
            float y2 = __shfl_sync(0xffffffffu, acc[kk][2], sl1);
            float y3 = __shfl_sync(0xffffffffu, acc[kk][3], sl1);
            uint32_t a[4];
            a[0] = fu((tg & 1) ? x1 : x0);
            a[1] = fu((tg & 1) ? x3 : x2v);
            a[2] = fu((tg & 1) ? y1 : y0);
            a[3] = fu((tg & 1) ? y3 : y2);
            #pragma unroll
            for (int nt = 0; nt < 4; nt++) {
                const float* Bp = sV + (kk * 8 + tg) * XS + h * HD + nt * 8 + g;
                uint32_t bfr[2] = { fu(Bp[0]), fu(Bp[4 * XS]) };
                mma8(accO[nt], a, bfr);
            }
        }

        // ---- store O rows (16 x 32 slice) ----
        const int r0 = mB + g, r1 = r0 + 8;
        #pragma unroll
        for (int nt = 0; nt < 4; nt++) {
            const int c = h * HD + nt * 8 + 2 * tg;
            if (r0 < NTOK)
                *reinterpret_cast<float2*>(xo + r0 * DIM + c) =
                    make_float2(accO[nt][0], accO[nt][1]);
            if (r1 < NTOK)
                *reinterpret_cast<float2*>(xo + r1 * DIM + c) =
                    make_float2(accO[nt][2], accO[nt][3]);
        }
    }
}

#define PROJ_SMEM ((128 * XS2 + 2 * 128 * WS2) * 4)
#define ATTN_SMEM ((3 * MPAD * XS) * 4)
#define QSCALE 0.17677669529663687f

extern "C" void kernel_launch(void* const* d_in, const int* in_sizes, int n_in,
                              void* d_out, int out_size)
{
    const float* query      = (const float*)d_in[0];
    const float* key        = (const float*)d_in[1];
    const float* value      = (const float*)d_in[2];
    const float* Wq         = (const float*)d_in[3];
    const float* bq         = (const float*)d_in[4];
    const float* Wk         = (const float*)d_in[5];
    const float* bk         = (const float*)d_in[6];
    const float* Wv         = (const float*)d_in[7];
    const float* bv         = (const float*)d_in[8];
    const float* bias_table = (const float*)d_in[9];
    const float* Wp         = (const float*)d_in[10];
    const float* bp         = (const float*)d_in[11];
    const float* mask       = (const float*)d_in[12];
    const int*   rel_index  = (const int*)d_in[13];
    float* out = (float*)d_out;

    float* q = nullptr; float* k = nullptr; float* v = nullptr; float* x2 = nullptr;
    cudaGetSymbolAddress((void**)&q,  g_q);
    cudaGetSymbolAddress((void**)&k,  g_k);
    cudaGetSymbolAddress((void**)&v,  g_v);
    cudaGetSymbolAddress((void**)&x2, g_x2);

    cudaFuncSetAttribute(proj_kernel,
                         cudaFuncAttributeMaxDynamicSharedMemorySize, PROJ_SMEM);
    cudaFuncSetAttribute(attn_kernel,
                         cudaFuncAttributeMaxDynamicSharedMemorySize, ATTN_SMEM);

    biasfrag_kernel<<<(NWIN * HEADS * 4 * 2 * 8 * 32) / 256, 256>>>(
        bias_table, rel_index, mask);

    proj_kernel<<<dim3(NROWS / 128, 3), 256, PROJ_SMEM>>>(
        query, key, value, Wq, Wk, Wv, bq, bk, bv, q, k, v,
        QSCALE, 1.f, 1.f);

    attn_kernel<<<NBLK, 256, ATTN_SMEM>>>(q, k, v, x2);

    proj_kernel<<<dim3(NROWS / 128, 1), 256, PROJ_SMEM>>>(
        x2, x2, x2, Wp, Wp, Wp, bp, bp, bp, out, out, out,
        1.f, 1.f, 1.f);
}

// round 7
// speedup vs baseline: 2.3467x; 1.2093x over previous
#include <cuda_runtime.h>
#include <cstdint>

#define NTOK 49
#define MPAD 64
#define DIM 128
#define HEADS 4
#define HD 32
#define NWIN 64
#define NBLK 4096
#define NROWS (NBLK * NTOK)          // 200704
#define XS 132   // padded stride for 64x128 attn tiles
#define XS2 132  // proj input tile stride
#define WS2 36   // proj weight k-chunk stride (32 + 4 pad)

// ---------------- global scratch (allocation-free) ----------------
__device__ float g_q[NROWS * DIM];
__device__ float g_k[NROWS * DIM];
__device__ float g_v[NROWS * DIM];
// fused (relbias + mask) in mma C-fragment layout:
// [win][h][mg][rs][nt][lane] float2
__device__ float2 g_biasF[NWIN * HEADS * 4 * 2 * 8 * 32];

__global__ void biasfrag_kernel(const float* __restrict__ bias_table,
                                const int* __restrict__ rel_index,
                                const float* __restrict__ mask)
{
    int idx = blockIdx.x * 256 + threadIdx.x;   // 2,097,152 total, exact grid
    int lane = idx & 31;
    int nt   = (idx >> 5) & 7;
    int rs   = (idx >> 8) & 1;
    int mg   = (idx >> 9) & 3;
    int h    = (idx >> 11) & 3;
    int win  = idx >> 13;                       // < 64
    int g = lane >> 2, tg = lane & 3;
    int r = mg * 16 + rs * 8 + g;
    int c0 = nt * 8 + 2 * tg;

    float2 v;
    if (c0 >= NTOK)      v.x = -1e30f;
    else if (r >= NTOK)  v.x = 0.f;
    else v.x = bias_table[rel_index[r * NTOK + c0] * HEADS + h]
             + mask[(win * NTOK + r) * NTOK + c0];
    int c1 = c0 + 1;
    if (c1 >= NTOK)      v.y = -1e30f;
    else if (r >= NTOK)  v.y = 0.f;
    else v.y = bias_table[rel_index[r * NTOK + c1] * HEADS + h]
             + mask[(win * NTOK + r) * NTOK + c1];

    g_biasF[idx] = v;
}

__device__ __forceinline__ float to_tf32(float x) {
    asm("cvt.rna.tf32.f32 %0, %0;" : "+f"(x));
    return x;
}
__device__ __forceinline__ uint32_t fu(float x) { return __float_as_uint(x); }

__device__ __forceinline__ void mma8(float c[4], const uint32_t a[4], const uint32_t b[2]) {
    asm volatile(
        "mma.sync.aligned.m16n8k8.row.col.f32.tf32.tf32.f32 "
        "{%0,%1,%2,%3}, {%4,%5,%6,%7}, {%8,%9}, {%0,%1,%2,%3};\n"
        : "+f"(c[0]), "+f"(c[1]), "+f"(c[2]), "+f"(c[3])
        : "r"(a[0]), "r"(a[1]), "r"(a[2]), "r"(a[3]), "r"(b[0]), "r"(b[1]));
}

// =====================================================================
// Projection GEMM (Q/K/V): unchanged from R5.
// =====================================================================
__global__ __launch_bounds__(256, 2)
void proj_kernel(const float* __restrict__ X0, const float* __restrict__ X1,
                 const float* __restrict__ X2,
                 const float* __restrict__ W0_, const float* __restrict__ W1_,
                 const float* __restrict__ W2_,
                 const float* __restrict__ B0_, const float* __restrict__ B1_,
                 const float* __restrict__ B2_,
                 float* __restrict__ O0_, float* __restrict__ O1_,
                 float* __restrict__ O2_,
                 float a0, float a1, float a2)
{
    extern __shared__ float sm[];
    float* sX = sm;                   // 128 x 132
    float* sW = sX + 128 * XS2;       // 2 x 128 x 36

    const float* X; const float* W; const float* Bb; float* O; float alpha;
    if (blockIdx.y == 0)      { X = X0; W = W0_; Bb = B0_; O = O0_; alpha = a0; }
    else if (blockIdx.y == 1) { X = X1; W = W1_; Bb = B1_; O = O1_; alpha = a1; }
    else                      { X = X2; W = W2_; Bb = B2_; O = O2_; alpha = a2; }

    const int tid  = threadIdx.x;
    const int warp = tid >> 5, lane = tid & 31;
    const int g = lane >> 2, tg = lane & 3;
    const int mBase = blockIdx.x * 128;

    const float4* gX = reinterpret_cast<const float4*>(X + mBase * DIM);
    #pragma unroll
    for (int t = 0; t < 16; t++) {
        int f = t * 256 + tid;
        int r = f >> 5, c4 = f & 31;
        float4 v = gX[f];
        v.x = to_tf32(v.x); v.y = to_tf32(v.y);
        v.z = to_tf32(v.z); v.w = to_tf32(v.w);
        *reinterpret_cast<float4*>(sX + r * XS2 + c4 * 4) = v;
    }
    const float4* gW = reinterpret_cast<const float4*>(W);
    #pragma unroll
    for (int t = 0; t < 4; t++) {
        int f = t * 256 + tid;
        int n = f >> 3, c4 = f & 7;
        float4 v = gW[n * 32 + c4];
        v.x = to_tf32(v.x); v.y = to_tf32(v.y);
        v.z = to_tf32(v.z); v.w = to_tf32(v.w);
        *reinterpret_cast<float4*>(sW + n * WS2 + c4 * 4) = v;
    }
    __syncthreads();

    const int wm = warp & 3;
    const int wn = warp >> 2;
    float acc[2][8][4];
    #pragma unroll
    for (int mt = 0; mt < 2; mt++)
        #pragma unroll
        for (int nt = 0; nt < 8; nt++)
            #pragma unroll
            for (int j = 0; j < 4; j++) acc[mt][nt][j] = 0.f;

    float4 wpre[4];
    #pragma unroll
    for (int kc = 0; kc < 4; kc++) {
        if (kc < 3) {
            #pragma unroll
            for (int t = 0; t < 4; t++) {
                int f = t * 256 + tid;
                wpre[t] = gW[(f >> 3) * 32 + (kc + 1) * 8 + (f & 7)];
            }
        }
        const float* buf = sW + (kc & 1) * 128 * WS2;
        #pragma unroll
        for (int ks = 0; ks < 4; ks++) {
            const int k = kc * 32 + ks * 8;
            uint32_t afr[2][4];
            #pragma unroll
            for (int mt = 0; mt < 2; mt++) {
                const float* Ap = sX + (wm * 32 + mt * 16 + g) * XS2 + k + tg;
                afr[mt][0] = fu(Ap[0]);
                afr[mt][1] = fu(Ap[8 * XS2]);
                afr[mt][2] = fu(Ap[4]);
                afr[mt][3] = fu(Ap[8 * XS2 + 4]);
            }
            #pragma unroll
            for (int nt = 0; nt < 8; nt++) {
                const float* Bp = buf + (wn * 64 + nt * 8 + g) * WS2 + ks * 8 + tg;
                uint32_t bfr[2] = { fu(Bp[0]), fu(Bp[4]) };
                mma8(acc[0][nt], afr[0], bfr);
                mma8(acc[1][nt], afr[1], bfr);
            }
        }
        if (kc < 3) {
            __syncthreads();
            float* dbuf = sW + ((kc + 1) & 1) * 128 * WS2;
            #pragma unroll
            for (int t = 0; t < 4; t++) {
                int f = t * 256 + tid;
                int n = f >> 3, c4 = f & 7;
                float4 v = wpre[t];
                v.x = to_tf32(v.x); v.y = to_tf32(v.y);
                v.z = to_tf32(v.z); v.w = to_tf32(v.w);
                *reinterpret_cast<float4*>(dbuf + n * WS2 + c4 * 4) = v;
            }
            __syncthreads();
        }
    }

    #pragma unroll
    for (int mt = 0; mt < 2; mt++) {
        const int r0 = mBase + wm * 32 + mt * 16 + g;
        #pragma unroll
        for (int nt = 0; nt < 8; nt++) {
            const int c = wn * 64 + nt * 8 + 2 * tg;
            const float b0 = Bb[c], b1 = Bb[c + 1];
            float2 v0 = make_float2((acc[mt][nt][0] + b0) * alpha,
                                    (acc[mt][nt][1] + b1) * alpha);
            *reinterpret_cast<float2*>(O + r0 * DIM + c) = v0;
            float2 v1 = make_float2((acc[mt][nt][2] + b0) * alpha,
                                    (acc[mt][nt][3] + b1) * alpha);
            *reinterpret_cast<float2*>(O + (r0 + 8) * DIM + c) = v1;
        }
    }
}

// =====================================================================
// Fused attention + output projection. Per window (4096 CTAs, 256 thr).
// Staging: batched unrolled LDG.128 (high MLP), then convert+STS.
// Attention in registers (as R5). Then O tile -> smem, GEMM O@Wp^T+bp
// with Wp k-chunk streamed from L2, write final out. smem 99KB, 2 CTAs/SM.
// =====================================================================
__global__ __launch_bounds__(256, 2)
void attn_proj_kernel(const float* __restrict__ gq, const float* __restrict__ gk,
                      const float* __restrict__ gv, const float* __restrict__ Wp,
                      const float* __restrict__ bp, float* __restrict__ out)
{
    extern __shared__ float sm[];
    float* sQ = sm;                // 64 x 132  (later: O tile)
    float* sK = sQ + MPAD * XS;    // 64 x 132  (later: Wp chunks 2 x 128 x 36)
    float* sV = sK + MPAD * XS;    // 64 x 132

    const int tid = threadIdx.x;
    const int warp = tid >> 5, lane = tid & 31;
    const int g = lane >> 2, tg = lane & 3;
    const int b = blockIdx.x;
    const int base = b * NTOK * DIM;

    // ---- batched staging: all loads issued before stores ----
    {
        const float4* Gq = reinterpret_cast<const float4*>(gq + base);
        const float4* Gk = reinterpret_cast<const float4*>(gk + base);
        const float4* Gv = reinterpret_cast<const float4*>(gv + base);
        float4 rq[6], rk[6], rv[6], tq, tk, tv;
        const bool hasTail = tid < 32;
        if (hasTail) {
            tq = Gq[1536 + tid]; tk = Gk[1536 + tid]; tv = Gv[1536 + tid];
        }
        #pragma unroll
        for (int t = 0; t < 6; t++) rq[t] = Gq[t * 256 + tid];
        #pragma unroll
        for (int t = 0; t < 6; t++) rk[t] = Gk[t * 256 + tid];
        #pragma unroll
        for (int t = 0; t < 6; t++) rv[t] = Gv[t * 256 + tid];

        #pragma unroll
        for (int t = 0; t < 6; t++) {
            int f = t * 256 + tid;
            int r = f >> 5, c4 = f & 31;
            float4 v;
            v = rq[t];
            v.x = to_tf32(v.x); v.y = to_tf32(v.y); v.z = to_tf32(v.z); v.w = to_tf32(v.w);
            *reinterpret_cast<float4*>(sQ + r * XS + c4 * 4) = v;
            v = rk[t];
            v.x = to_tf32(v.x); v.y = to_tf32(v.y); v.z = to_tf32(v.z); v.w = to_tf32(v.w);
            *reinterpret_cast<float4*>(sK + r * XS + c4 * 4) = v;
            v = rv[t];
            v.x = to_tf32(v.x); v.y = to_tf32(v.y); v.z = to_tf32(v.z); v.w = to_tf32(v.w);
            *reinterpret_cast<float4*>(sV + r * XS + c4 * 4) = v;
        }
        if (hasTail) {
            int c4 = tid;   // row 48
            float4 v;
            v = tq;
            v.x = to_tf32(v.x); v.y = to_tf32(v.y); v.z = to_tf32(v.z); v.w = to_tf32(v.w);
            *reinterpret_cast<float4*>(sQ + 48 * XS + c4 * 4) = v;
            v = tk;
            v.x = to_tf32(v.x); v.y = to_tf32(v.y); v.z = to_tf32(v.z); v.w = to_tf32(v.w);
            *reinterpret_cast<float4*>(sK + 48 * XS + c4 * 4) = v;
            v = tv;
            v.x = to_tf32(v.x); v.y = to_tf32(v.y); v.z = to_tf32(v.z); v.w = to_tf32(v.w);
            *reinterpret_cast<float4*>(sV + 48 * XS + c4 * 4) = v;
        }
        // zero rows 49..63 (cols 0..127) for each tile
        const float4 z = make_float4(0.f, 0.f, 0.f, 0.f);
        #pragma unroll
        for (int t = 0; t < 2; t++) {
            int f = t * 256 + tid;
            if (f < 480) {
                int r = 49 + (f >> 5), c4 = f & 31;
                *reinterpret_cast<float4*>(sQ + r * XS + c4 * 4) = z;
                *reinterpret_cast<float4*>(sK + r * XS + c4 * 4) = z;
                *reinterpret_cast<float4*>(sV + r * XS + c4 * 4) = z;
            }
        }
    }
    __syncthreads();

    const float2* bwin = g_biasF + (size_t)(b & (NWIN - 1)) * (HEADS * 4 * 2 * 8 * 32);

    const int sl0 = (lane & ~3) | (tg >> 1);   // C->A permute source: cols tg
    const int sl1 = sl0 + 2;                   // cols tg+4

    float accO[2][4][4];
    #pragma unroll
    for (int task = 0; task < 2; task++)
        #pragma unroll
        for (int nt = 0; nt < 4; nt++)
            #pragma unroll
            for (int j = 0; j < 4; j++) accO[task][nt][j] = 0.f;

    #pragma unroll
    for (int task = 0; task < 2; task++) {
        const int rg = task * 8 + warp;        // 0..15
        const int h  = rg >> 2;
        const int mg = rg & 3;
        const int mB = mg * 16;

        // ---- S = q_h @ k_h^T, 16x64 per warp (q pre-scaled) ----
        float acc[8][4];
        #pragma unroll
        for (int nt = 0; nt < 8; nt++)
            #pragma unroll
            for (int j = 0; j < 4; j++) acc[nt][j] = 0.f;

        #pragma unroll
        for (int kk = 0; kk < 4; kk++) {
            const int k = h * HD + kk * 8;
            uint32_t a[4];
            const float* Ap = sQ + (mB + g) * XS + k + tg;
            a[0] = fu(Ap[0]);
            a[1] = fu(Ap[8 * XS]);
            a[2] = fu(Ap[4]);
            a[3] = fu(Ap[8 * XS + 4]);
            #pragma unroll
            for (int nt = 0; nt < 8; nt++) {
                const float* Bp = sK + (nt * 8 + g) * XS + k + tg;
                uint32_t bfr[2] = { fu(Bp[0]), fu(Bp[4]) };
                mma8(acc[nt], a, bfr);
            }
        }

        // ---- fused bias fragments (16 coalesced LDG.64) ----
        const float2* bfp = bwin + ((h * 4 + mg) * 2 * 8) * 32 + lane;
        float2 bR[2][8];
        #pragma unroll
        for (int rs = 0; rs < 2; rs++)
            #pragma unroll
            for (int nt = 0; nt < 8; nt++)
                bR[rs][nt] = bfp[(rs * 8 + nt) * 32];

        // ---- bias + softmax, in-register; acc becomes P ----
        #pragma unroll
        for (int rs = 0; rs < 2; rs++) {
            float lv[16];
            #pragma unroll
            for (int nt = 0; nt < 8; nt++) {
                lv[nt * 2 + 0] = acc[nt][rs * 2 + 0] + bR[rs][nt].x;
                lv[nt * 2 + 1] = acc[nt][rs * 2 + 1] + bR[rs][nt].y;
            }
            float m = lv[0];
            #pragma unroll
            for (int i = 1; i < 16; i++) m = fmaxf(m, lv[i]);
            m = fmaxf(m, __shfl_xor_sync(0xffffffffu, m, 1));
            m = fmaxf(m, __shfl_xor_sync(0xffffffffu, m, 2));
            float s = 0.f;
            #pragma unroll
            for (int i = 0; i < 16; i++) { lv[i] = __expf(lv[i] - m); s += lv[i]; }
            s += __shfl_xor_sync(0xffffffffu, s, 1);
            s += __shfl_xor_sync(0xffffffffu, s, 2);
            const float inv = 1.f / s;
            #pragma unroll
            for (int nt = 0; nt < 8; nt++) {
                acc[nt][rs * 2 + 0] = to_tf32(lv[nt * 2 + 0] * inv);
                acc[nt][rs * 2 + 1] = to_tf32(lv[nt * 2 + 1] * inv);
            }
        }

        // ---- O = P @ V_h: 16x32 per warp; A-fragments via quad shfl ----
        #pragma unroll
        for (int kk = 0; kk < 8; kk++) {
            float x0 = __shfl_sync(0xffffffffu, acc[kk][0], sl0);
            float x1 = __shfl_sync(0xffffffffu, acc[kk][1], sl0);
            float x2v = __shfl_sync(0xffffffffu, acc[kk][2], sl0);
            float x3 = __shfl_sync(0xffffffffu, acc[kk][3], sl0);
            float y0 = __shfl_sync(0xffffffffu, acc[kk][0], sl1);
            float y1 = __shfl_sync(0xffffffffu, acc[kk][1], sl1);
            float y2 = __shfl_sync(0xffffffffu, acc[kk][2], sl1);
            float y3 = __shfl_sync(0xffffffffu, acc[kk][3], sl1);
            uint32_t a[4];
            a[0] = fu((tg & 1) ? x1 : x0);
            a[1] = fu((tg & 1) ? x3 : x2v);
            a[2] = fu((tg & 1) ? y1 : y0);
            a[3] = fu((tg & 1) ? y3 : y2);
            #pragma unroll
            for (int nt = 0; nt < 4; nt++) {
                const float* Bp = sV + (kk * 8 + tg) * XS + h * HD + nt * 8 + g;
                uint32_t bfr[2] = { fu(Bp[0]), fu(Bp[4 * XS]) };
                mma8(accO[task][nt], a, bfr);
            }
        }
    }
    __syncthreads();   // all warps done reading sQ/sK/sV

    // ---- store O tile into sQ region (tf32-rounded) ----
    #pragma unroll
    for (int task = 0; task < 2; task++) {
        const int rg = task * 8 + warp;
        const int h  = rg >> 2;
        const int mB = (rg & 3) * 16;
        const int r0 = mB + g, r1 = r0 + 8;
        #pragma unroll
        for (int nt = 0; nt < 4; nt++) {
            const int c = h * HD + nt * 8 + 2 * tg;
            float2 v0 = make_float2(to_tf32(accO[task][nt][0]), to_tf32(accO[task][nt][1]));
            *reinterpret_cast<float2*>(sQ + r0 * XS + c) = v0;
            float2 v1 = make_float2(to_tf32(accO[task][nt][2]), to_tf32(accO[task][nt][3]));
            *reinterpret_cast<float2*>(sQ + r1 * XS + c) = v1;
        }
    }

    // ---- Wp chunk 0 -> buffer 0 (sK region) ----
    float* sW = sK;                      // 2 x 128 x 36 (spills into sV region)
    const float4* gW = reinterpret_cast<const float4*>(Wp);
    #pragma unroll
    for (int t = 0; t < 4; t++) {
        int f = t * 256 + tid;
        int n = f >> 3, c4 = f & 7;
        float4 v = gW[n * 32 + c4];
        v.x = to_tf32(v.x); v.y = to_tf32(v.y);
        v.z = to_tf32(v.z); v.w = to_tf32(v.w);
        *reinterpret_cast<float4*>(sW + n * WS2 + c4 * 4) = v;
    }
    __syncthreads();

    // ---- GEMM: out[64,128] = O @ Wp^T + bp ----
    const int wm = warp & 3;     // 4 m-chunks of 16 rows
    const int wn = warp >> 2;    // 2 n-chunks of 64 cols
    float acc2[8][4];
    #pragma unroll
    for (int nt = 0; nt < 8; nt++)
        #pragma unroll
        for (int j = 0; j < 4; j++) acc2[nt][j] = 0.f;

    float4 wpre[4];
    #pragma unroll
    for (int kc = 0; kc < 4; kc++) {
        if (kc < 3) {
            #pragma unroll
            for (int t = 0; t < 4; t++) {
                int f = t * 256 + tid;
                wpre[t] = gW[(f >> 3) * 32 + (kc + 1) * 8 + (f & 7)];
            }
        }
        const float* buf = sW + (kc & 1) * 128 * WS2;
        #pragma unroll
        for (int ks = 0; ks < 4; ks++) {
            const int k = kc * 32 + ks * 8;
            uint32_t afr[4];
            const float* Ap = sQ + (wm * 16 + g) * XS + k + tg;
            afr[0] = fu(Ap[0]);
            afr[1] = fu(Ap[8 * XS]);
            afr[2] = fu(Ap[4]);
            afr[3] = fu(Ap[8 * XS + 4]);
            #pragma unroll
            for (int nt = 0; nt < 8; nt++) {
                const float* Bp = buf + (wn * 64 + nt * 8 + g) * WS2 + ks * 8 + tg;
                uint32_t bfr[2] = { fu(Bp[0]), fu(Bp[4]) };
                mma8(acc2[nt], afr, bfr);
            }
        }
        if (kc < 3) {
            __syncthreads();
            float* dbuf = sW + ((kc + 1) & 1) * 128 * WS2;
            #pragma unroll
            for (int t = 0; t < 4; t++) {
                int f = t * 256 + tid;
                int n = f >> 3, c4 = f & 7;
                float4 v = wpre[t];
                v.x = to_tf32(v.x); v.y = to_tf32(v.y);
                v.z = to_tf32(v.z); v.w = to_tf32(v.w);
                *reinterpret_cast<float4*>(dbuf + n * WS2 + c4 * 4) = v;
            }
            __syncthreads();
        }
    }

    // ---- epilogue: +bp, write final out ----
    const int r0 = wm * 16 + g, r1 = r0 + 8;
    #pragma unroll
    for (int nt = 0; nt < 8; nt++) {
        const int c = wn * 64 + nt * 8 + 2 * tg;
        const float b0 = bp[c], b1 = bp[c + 1];
        if (r0 < NTOK)
            *reinterpret_cast<float2*>(out + base + r0 * DIM + c) =
                make_float2(acc2[nt][0] + b0, acc2[nt][1] + b1);
        if (r1 < NTOK)
            *reinterpret_cast<float2*>(out + base + r1 * DIM + c) =
                make_float2(acc2[nt][2] + b0, acc2[nt][3] + b1);
    }
}

#define PROJ_SMEM ((128 * XS2 + 2 * 128 * WS2) * 4)
#define ATTN_SMEM ((3 * MPAD * XS) * 4)
#define QSCALE 0.17677669529663687f

extern "C" void kernel_launch(void* const* d_in, const int* in_sizes, int n_in,
                              void* d_out, int out_size)
{
    const float* query      = (const float*)d_in[0];
    const float* key        = (const float*)d_in[1];
    const float* value      = (const float*)d_in[2];
    const float* Wq         = (const float*)d_in[3];
    const float* bq         = (const float*)d_in[4];
    const float* Wk         = (const float*)d_in[5];
    const float* bk         = (const float*)d_in[6];
    const float* Wv         = (const float*)d_in[7];
    const float* bv         = (const float*)d_in[8];
    const float* bias_table = (const float*)d_in[9];
    const float* Wp         = (const float*)d_in[10];
    const float* bp         = (const float*)d_in[11];
    const float* mask       = (const float*)d_in[12];
    const int*   rel_index  = (const int*)d_in[13];
    float* out = (float*)d_out;

    float* q = nullptr; float* k = nullptr; float* v = nullptr;
    cudaGetSymbolAddress((void**)&q,  g_q);
    cudaGetSymbolAddress((void**)&k,  g_k);
    cudaGetSymbolAddress((void**)&v,  g_v);

    cudaFuncSetAttribute(proj_kernel,
                         cudaFuncAttributeMaxDynamicSharedMemorySize, PROJ_SMEM);
    cudaFuncSetAttribute(attn_proj_kernel,
                         cudaFuncAttributeMaxDynamicSharedMemorySize, ATTN_SMEM);

    biasfrag_kernel<<<(NWIN * HEADS * 4 * 2 * 8 * 32) / 256, 256>>>(
        bias_table, rel_index, mask);

    proj_kernel<<<dim3(NROWS / 128, 3), 256, PROJ_SMEM>>>(
        query, key, value, Wq, Wk, Wv, bq, bk, bv, q, k, v,
        QSCALE, 1.f, 1.f);

    attn_proj_kernel<<<NBLK, 256, ATTN_SMEM>>>(q, k, v, Wp, bp, out);
}

// round 11
// speedup vs baseline: 2.4578x; 1.0474x over previous
#include <cuda_runtime.h>
#include <cuda_fp16.h>
#include <cstdint>

#define NTOK 49
#define MPAD 64
#define DIM 128
#define HEADS 4
#define HD 32
#define NWIN 64
#define NBLK 4096
#define NROWS (NBLK * NTOK)          // 200704
#define XS 132   // padded stride for 64x128 attn tiles
#define XS2 132  // proj input tile stride
#define WS2 36   // proj weight k-chunk stride (32 + 4 pad)

// ---------------- global scratch (allocation-free) ----------------
__device__ __half g_q[NROWS * DIM];
__device__ __half g_k[NROWS * DIM];
__device__ __half g_v[NROWS * DIM];
// fused (relbias + mask) in mma C-fragment layout:
// [win][h][mg][rs][nt][lane] float2
__device__ float2 g_biasF[NWIN * HEADS * 4 * 2 * 8 * 32];

__global__ void biasfrag_kernel(const float* __restrict__ bias_table,
                                const int* __restrict__ rel_index,
                                const float* __restrict__ mask)
{
    int idx = blockIdx.x * 256 + threadIdx.x;   // 2,097,152 total, exact grid
    int lane = idx & 31;
    int nt   = (idx >> 5) & 7;
    int rs   = (idx >> 8) & 1;
    int mg   = (idx >> 9) & 3;
    int h    = (idx >> 11) & 3;
    int win  = idx >> 13;                       // < 64
    int g = lane >> 2, tg = lane & 3;
    int r = mg * 16 + rs * 8 + g;
    int c0 = nt * 8 + 2 * tg;

    float2 v;
    if (c0 >= NTOK)      v.x = -1e30f;
    else if (r >= NTOK)  v.x = 0.f;
    else v.x = bias_table[rel_index[r * NTOK + c0] * HEADS + h]
             + mask[(win * NTOK + r) * NTOK + c0];
    int c1 = c0 + 1;
    if (c1 >= NTOK)      v.y = -1e30f;
    else if (r >= NTOK)  v.y = 0.f;
    else v.y = bias_table[rel_index[r * NTOK + c1] * HEADS + h]
             + mask[(win * NTOK + r) * NTOK + c1];

    g_biasF[idx] = v;
}

__device__ __forceinline__ float to_tf32(float x) {
    asm("cvt.rna.tf32.f32 %0, %0;" : "+f"(x));
    return x;
}
__device__ __forceinline__ uint32_t fu(float x) { return __float_as_uint(x); }

__device__ __forceinline__ void mma8(float c[4], const uint32_t a[4], const uint32_t b[2]) {
    asm volatile(
        "mma.sync.aligned.m16n8k8.row.col.f32.tf32.tf32.f32 "
        "{%0,%1,%2,%3}, {%4,%5,%6,%7}, {%8,%9}, {%0,%1,%2,%3};\n"
        : "+f"(c[0]), "+f"(c[1]), "+f"(c[2]), "+f"(c[3])
        : "r"(a[0]), "r"(a[1]), "r"(a[2]), "r"(a[3]), "r"(b[0]), "r"(b[1]));
}

// unpack 8 halves (uint4) -> 8 floats into smem (fp16 is exact in tf32)
__device__ __forceinline__ void st8h(float* dst, uint4 u) {
    float2 a = __half22float2(*reinterpret_cast<__half2*>(&u.x));
    float2 b = __half22float2(*reinterpret_cast<__half2*>(&u.y));
    float2 c = __half22float2(*reinterpret_cast<__half2*>(&u.z));
    float2 d = __half22float2(*reinterpret_cast<__half2*>(&u.w));
    *reinterpret_cast<float4*>(dst)     = make_float4(a.x, a.y, b.x, b.y);
    *reinterpret_cast<float4*>(dst + 4) = make_float4(c.x, c.y, d.x, d.y);
}

// =====================================================================
// Projection GEMM (Q/K/V): X fp32 in, fp16 out.
// =====================================================================
__global__ __launch_bounds__(256, 2)
void proj_kernel(const float* __restrict__ X0, const float* __restrict__ X1,
                 const float* __restrict__ X2,
                 const float* __restrict__ W0_, const float* __restrict__ W1_,
                 const float* __restrict__ W2_,
                 const float* __restrict__ B0_, const float* __restrict__ B1_,
                 const float* __restrict__ B2_,
                 __half* __restrict__ O0_, __half* __restrict__ O1_,
                 __half* __restrict__ O2_,
                 float a0, float a1, float a2)
{
    extern __shared__ float sm[];
    float* sX = sm;                   // 128 x 132
    float* sW = sX + 128 * XS2;       // 2 x 128 x 36

    const float* X; const float* W; const float* Bb; __half* O; float alpha;
    if (blockIdx.y == 0)      { X = X0; W = W0_; Bb = B0_; O = O0_; alpha = a0; }
    else if (blockIdx.y == 1) { X = X1; W = W1_; Bb = B1_; O = O1_; alpha = a1; }
    else                      { X = X2; W = W2_; Bb = B2_; O = O2_; alpha = a2; }

    const int tid  = threadIdx.x;
    const int warp = tid >> 5, lane = tid & 31;
    const int g = lane >> 2, tg = lane & 3;
    const int mBase = blockIdx.x * 128;

    const float4* gX = reinterpret_cast<const float4*>(X + mBase * DIM);
    #pragma unroll
    for (int t = 0; t < 16; t++) {
        int f = t * 256 + tid;
        int r = f >> 5, c4 = f & 31;
        float4 v = gX[f];
        v.x = to_tf32(v.x); v.y = to_tf32(v.y);
        v.z = to_tf32(v.z); v.w = to_tf32(v.w);
        *reinterpret_cast<float4*>(sX + r * XS2 + c4 * 4) = v;
    }
    const float4* gW = reinterpret_cast<const float4*>(W);
    #pragma unroll
    for (int t = 0; t < 4; t++) {
        int f = t * 256 + tid;
        int n = f >> 3, c4 = f & 7;
        float4 v = gW[n * 32 + c4];
        v.x = to_tf32(v.x); v.y = to_tf32(v.y);
        v.z = to_tf32(v.z); v.w = to_tf32(v.w);
        *reinterpret_cast<float4*>(sW + n * WS2 + c4 * 4) = v;
    }
    __syncthreads();

    const int wm = warp & 3;
    const int wn = warp >> 2;
    float acc[2][8][4];
    #pragma unroll
    for (int mt = 0; mt < 2; mt++)
        #pragma unroll
        for (int nt = 0; nt < 8; nt++)
            #pragma unroll
            for (int j = 0; j < 4; j++) acc[mt][nt][j] = 0.f;

    float4 wpre[4];
    #pragma unroll
    for (int kc = 0; kc < 4; kc++) {
        if (kc < 3) {
            #pragma unroll
            for (int t = 0; t < 4; t++) {
                int f = t * 256 + tid;
                wpre[t] = gW[(f >> 3) * 32 + (kc + 1) * 8 + (f & 7)];
            }
        }
        const float* buf = sW + (kc & 1) * 128 * WS2;
        #pragma unroll
        for (int ks = 0; ks < 4; ks++) {
            const int k = kc * 32 + ks * 8;
            uint32_t afr[2][4];
            #pragma unroll
            for (int mt = 0; mt < 2; mt++) {
                const float* Ap = sX + (wm * 32 + mt * 16 + g) * XS2 + k + tg;
                afr[mt][0] = fu(Ap[0]);
                afr[mt][1] = fu(Ap[8 * XS2]);
                afr[mt][2] = fu(Ap[4]);
                afr[mt][3] = fu(Ap[8 * XS2 + 4]);
            }
            #pragma unroll
            for (int nt = 0; nt < 8; nt++) {
                const float* Bp = buf + (wn * 64 + nt * 8 + g) * WS2 + ks * 8 + tg;
                uint32_t bfr[2] = { fu(Bp[0]), fu(Bp[4]) };
                mma8(acc[0][nt], afr[0], bfr);
                mma8(acc[1][nt], afr[1], bfr);
            }
        }
        if (kc < 3) {
            __syncthreads();
            float* dbuf = sW + ((kc + 1) & 1) * 128 * WS2;
            #pragma unroll
            for (int t = 0; t < 4; t++) {
                int f = t * 256 + tid;
                int n = f >> 3, c4 = f & 7;
                float4 v = wpre[t];
                v.x = to_tf32(v.x); v.y = to_tf32(v.y);
                v.z = to_tf32(v.z); v.w = to_tf32(v.w);
                *reinterpret_cast<float4*>(dbuf + n * WS2 + c4 * 4) = v;
            }
            __syncthreads();
        }
    }

    #pragma unroll
    for (int mt = 0; mt < 2; mt++) {
        const int r0 = mBase + wm * 32 + mt * 16 + g;
        #pragma unroll
        for (int nt = 0; nt < 8; nt++) {
            const int c = wn * 64 + nt * 8 + 2 * tg;
            const float b0 = Bb[c], b1 = Bb[c + 1];
            __half2 h0 = __floats2half2_rn((acc[mt][nt][0] + b0) * alpha,
                                           (acc[mt][nt][1] + b1) * alpha);
            *reinterpret_cast<__half2*>(O + r0 * DIM + c) = h0;
            __half2 h1 = __floats2half2_rn((acc[mt][nt][2] + b0) * alpha,
                                           (acc[mt][nt][3] + b1) * alpha);
            *reinterpret_cast<__half2*>(O + (r0 + 8) * DIM + c) = h1;
        }
    }
}

// =====================================================================
// Fused attention + output projection. Per window (4096 CTAs, 256 thr).
// q/k/v read as fp16 (batched LDG.128, 8 halves each), expanded to fp32
// smem (exact). Attention in registers; then O@Wp^T+bp -> out.
// =====================================================================
__global__ __launch_bounds__(256, 2)
void attn_proj_kernel(const __half* __restrict__ gq, const __half* __restrict__ gk,
                      const __half* __restrict__ gv, const float* __restrict__ Wp,
                      const float* __restrict__ bp, float* __restrict__ out)
{
    extern __shared__ float sm[];
    float* sQ = sm;                // 64 x 132  (later: O tile)
    float* sK = sQ + MPAD * XS;    // 64 x 132  (later: Wp chunks 2 x 128 x 36)
    float* sV = sK + MPAD * XS;    // 64 x 132

    const int tid = threadIdx.x;
    const int warp = tid >> 5, lane = tid & 31;
    const int g = lane >> 2, tg = lane & 3;
    const int b = blockIdx.x;
    const int base = b * NTOK * DIM;

    // ---- batched staging: 784 uint4 per tile (8 halves each) ----
    {
        const uint4* Gq = reinterpret_cast<const uint4*>(gq + base);
        const uint4* Gk = reinterpret_cast<const uint4*>(gk + base);
        const uint4* Gv = reinterpret_cast<const uint4*>(gv + base);
        uint4 rq[3], rk[3], rv[3], tq, tk, tv;
        const bool hasTail = tid < 16;
        if (hasTail) {
            tq = Gq[768 + tid]; tk = Gk[768 + tid]; tv = Gv[768 + tid];
        }
        #pragma unroll
        for (int t = 0; t < 3; t++) rq[t] = Gq[t * 256 + tid];
        #pragma unroll
        for (int t = 0; t < 3; t++) rk[t] = Gk[t * 256 + tid];
        #pragma unroll
        for (int t = 0; t < 3; t++) rv[t] = Gv[t * 256 + tid];

        #pragma unroll
        for (int t = 0; t < 3; t++) {
            int f = t * 256 + tid;
            int r = f >> 4, c8 = f & 15;
            st8h(sQ + r * XS + c8 * 8, rq[t]);
            st8h(sK + r * XS + c8 * 8, rk[t]);
            st8h(sV + r * XS + c8 * 8, rv[t]);
        }
        if (hasTail) {
            int f = 768 + tid;
            int r = f >> 4, c8 = f & 15;     // row 48
            st8h(sQ + r * XS + c8 * 8, tq);
            st8h(sK + r * XS + c8 * 8, tk);
            st8h(sV + r * XS + c8 * 8, tv);
        }
        // zero rows 49..63 (cols 0..127) for each tile
        const float4 z = make_float4(0.f, 0.f, 0.f, 0.f);
        #pragma unroll
        for (int t = 0; t < 2; t++) {
            int f = t * 256 + tid;
            if (f < 480) {
                int r = 49 + (f >> 5), c4 = f & 31;
                *reinterpret_cast<float4*>(sQ + r * XS + c4 * 4) = z;
                *reinterpret_cast<float4*>(sK + r * XS + c4 * 4) = z;
                *reinterpret_cast<float4*>(sV + r * XS + c4 * 4) = z;
            }
        }
    }
    __syncthreads();

    const float2* bwin = g_biasF + (size_t)(b & (NWIN - 1)) * (HEADS * 4 * 2 * 8 * 32);

    const int sl0 = (lane & ~3) | (tg >> 1);   // C->A permute source: cols tg
    const int sl1 = sl0 + 2;                   // cols tg+4

    float accO[2][4][4];
    #pragma unroll
    for (int task = 0; task < 2; task++)
        #pragma unroll
        for (int nt = 0; nt < 4; nt++)
            #pragma unroll
            for (int j = 0; j < 4; j++) accO[task][nt][j] = 0.f;

    #pragma unroll
    for (int task = 0; task < 2; task++) {
        const int rg = task * 8 + warp;        // 0..15
        const int h  = rg >> 2;
        const int mg = rg & 3;
        const int mB = mg * 16;

        // ---- S = q_h @ k_h^T, 16x64 per warp (q pre-scaled) ----
        float acc[8][4];
        #pragma unroll
        for (int nt = 0; nt < 8; nt++)
            #pragma unroll
            for (int j = 0; j < 4; j++) acc[nt][j] = 0.f;

        #pragma unroll
        for (int kk = 0; kk < 4; kk++) {
            const int k = h * HD + kk * 8;
            uint32_t a[4];
            const float* Ap = sQ + (mB + g) * XS + k + tg;
            a[0] = fu(Ap[0]);
            a[1] = fu(Ap[8 * XS]);
            a[2] = fu(Ap[4]);
            a[3] = fu(Ap[8 * XS + 4]);
            #pragma unroll
            for (int nt = 0; nt < 8; nt++) {
                const float* Bp = sK + (nt * 8 + g) * XS + k + tg;
                uint32_t bfr[2] = { fu(Bp[0]), fu(Bp[4]) };
                mma8(acc[nt], a, bfr);
            }
        }

        // ---- fused bias fragments (16 coalesced LDG.64) ----
        const float2* bfp = bwin + ((h * 4 + mg) * 2 * 8) * 32 + lane;
        float2 bR[2][8];
        #pragma unroll
        for (int rs = 0; rs < 2; rs++)
            #pragma unroll
            for (int nt = 0; nt < 8; nt++)
                bR[rs][nt] = bfp[(rs * 8 + nt) * 32];

        // ---- bias + softmax, in-register; acc becomes P ----
        #pragma unroll
        for (int rs = 0; rs < 2; rs++) {
            float lv[16];
            #pragma unroll
            for (int nt = 0; nt < 8; nt++) {
                lv[nt * 2 + 0] = acc[nt][rs * 2 + 0] + bR[rs][nt].x;
                lv[nt * 2 + 1] = acc[nt][rs * 2 + 1] + bR[rs][nt].y;
            }
            float m = lv[0];
            #pragma unroll
            for (int i = 1; i < 16; i++) m = fmaxf(m, lv[i]);
            m = fmaxf(m, __shfl_xor_sync(0xffffffffu, m, 1));
            m = fmaxf(m, __shfl_xor_sync(0xffffffffu, m, 2));
            float s = 0.f;
            #pragma unroll
            for (int i = 0; i < 16; i++) { lv[i] = __expf(lv[i] - m); s += lv[i]; }
            s += __shfl_xor_sync(0xffffffffu, s, 1);
            s += __shfl_xor_sync(0xffffffffu, s, 2);
            const float inv = 1.f / s;
            #pragma unroll
            for (int nt = 0; nt < 8; nt++) {
                acc[nt][rs * 2 + 0] = to_tf32(lv[nt * 2 + 0] * inv);
                acc[nt][rs * 2 + 1] = to_tf32(lv[nt * 2 + 1] * inv);
            }
        }

        // ---- O = P @ V_h: 16x32 per warp; A-fragments via quad shfl ----
        #pragma unroll
        for (int kk = 0; kk < 8; kk++) {
            float x0 = __shfl_sync(0xffffffffu, acc[kk][0], sl0);
            float x1 = __shfl_sync(0xffffffffu, acc[kk][1], sl0);
            float x2v = __shfl_sync(0xffffffffu, acc[kk][2], sl0);
            float x3 = __shfl_sync(0xffffffffu, acc[kk][3], sl0);
            float y0 = __shfl_sync(0xffffffffu, acc[kk][0], sl1);
            float y1 = __shfl_sync(0xffffffffu, acc[kk][1], sl1);
            float y2 = __shfl_sync(0xffffffffu, acc[kk][2], sl1);
            float y3 = __shfl_sync(0xffffffffu, acc[kk][3], sl1);
            uint32_t a[4];
            a[0] = fu((tg & 1) ? x1 : x0);
            a[1] = fu((tg & 1) ? x3 : x2v);
            a[2] = fu((tg & 1) ? y1 : y0);
            a[3] = fu((tg & 1) ? y3 : y2);
            #pragma unroll
            for (int nt = 0; nt < 4; nt++) {
                const float* Bp = sV + (kk * 8 + tg) * XS + h * HD + nt * 8 + g;
                uint32_t bfr[2] = { fu(Bp[0]), fu(Bp[4 * XS]) };
                mma8(accO[task][nt], a, bfr);
            }
        }
    }
    __syncthreads();   // all warps done reading sQ/sK/sV

    // ---- store O tile into sQ region (tf32-rounded) ----
    #pragma unroll
    for (int task = 0; task < 2; task++) {
        const int rg = task * 8 + warp;
        const int h  = rg >> 2;
        const int mB = (rg & 3) * 16;
        const int r0 = mB + g, r1 = r0 + 8;
        #pragma unroll
        for (int nt = 0; nt < 4; nt++) {
            const int c = h * HD + nt * 8 + 2 * tg;
            float2 v0 = make_float2(to_tf32(accO[task][nt][0]), to_tf32(accO[task][nt][1]));
            *reinterpret_cast<float2*>(sQ + r0 * XS + c) = v0;
            float2 v1 = make_float2(to_tf32(accO[task][nt][2]), to_tf32(accO[task][nt][3]));
            *reinterpret_cast<float2*>(sQ + r1 * XS + c) = v1;
        }
    }

    // ---- Wp chunk 0 -> buffer 0 (sK region) ----
    float* sW = sK;                      // 2 x 128 x 36 (spills into sV region)
    const float4* gW = reinterpret_cast<const float4*>(Wp);
    #pragma unroll
    for (int t = 0; t < 4; t++) {
        int f = t * 256 + tid;
        int n = f >> 3, c4 = f & 7;
        float4 v = gW[n * 32 + c4];
        v.x = to_tf32(v.x); v.y = to_tf32(v.y);
        v.z = to_tf32(v.z); v.w = to_tf32(v.w);
        *reinterpret_cast<float4*>(sW + n * WS2 + c4 * 4) = v;
    }
    __syncthreads();

    // ---- GEMM: out[64,128] = O @ Wp^T + bp ----
    const int wm = warp & 3;     // 4 m-chunks of 16 rows
    const int wn = warp >> 2;    // 2 n-chunks of 64 cols
    float acc2[8][4];
    #pragma unroll
    for (int nt = 0; nt < 8; nt++)
        #pragma unroll
        for (int j = 0; j < 4; j++) acc2[nt][j] = 0.f;

    float4 wpre[4];
    #pragma unroll
    for (int kc = 0; kc < 4; kc++) {
        if (kc < 3) {
            #pragma unroll
            for (int t = 0; t < 4; t++) {
                int f = t * 256 + tid;
                wpre[t] = gW[(f >> 3) * 32 + (kc + 1) * 8 + (f & 7)];
            }
        }
        const float* buf = sW + (kc & 1) * 128 * WS2;
        #pragma unroll
        for (int ks = 0; ks < 4; ks++) {
            const int k = kc * 32 + ks * 8;
            uint32_t afr[4];
            const float* Ap = sQ + (wm * 16 + g) * XS + k + tg;
            afr[0] = fu(Ap[0]);
            afr[1] = fu(Ap[8 * XS]);
            afr[2] = fu(Ap[4]);
            afr[3] = fu(Ap[8 * XS + 4]);
            #pragma unroll
            for (int nt = 0; nt < 8; nt++) {
                const float* Bp = buf + (wn * 64 + nt * 8 + g) * WS2 + ks * 8 + tg;
                uint32_t bfr[2] = { fu(Bp[0]), fu(Bp[4]) };
                mma8(acc2[nt], afr, bfr);
            }
        }
        if (kc < 3) {
            __syncthreads();
            float* dbuf = sW + ((kc + 1) & 1) * 128 * WS2;
            #pragma unroll
            for (int t = 0; t < 4; t++) {
                int f = t * 256 + tid;
                int n = f >> 3, c4 = f & 7;
                float4 v = wpre[t];
                v.x = to_tf32(v.x); v.y = to_tf32(v.y);
                v.z = to_tf32(v.z); v.w = to_tf32(v.w);
                *reinterpret_cast<float4*>(dbuf + n * WS2 + c4 * 4) = v;
            }
            __syncthreads();
        }
    }

    // ---- epilogue: +bp, write final out ----
    const int r0 = wm * 16 + g, r1 = r0 + 8;
    #pragma unroll
    for (int nt = 0; nt < 8; nt++) {
        const int c = wn * 64 + nt * 8 + 2 * tg;
        const float b0 = bp[c], b1 = bp[c + 1];
        if (r0 < NTOK)
            *reinterpret_cast<float2*>(out + base + r0 * DIM + c) =
                make_float2(acc2[nt][0] + b0, acc2[nt][1] + b1);
        if (r1 < NTOK)
            *reinterpret_cast<float2*>(out + base + r1 * DIM + c) =
                make_float2(acc2[nt][2] + b0, acc2[nt][3] + b1);
    }
}

#define PROJ_SMEM ((128 * XS2 + 2 * 128 * WS2) * 4)
#define ATTN_SMEM ((3 * MPAD * XS) * 4)
#define QSCALE 0.17677669529663687f

extern "C" void kernel_launch(void* const* d_in, const int* in_sizes, int n_in,
                              void* d_out, int out_size)
{
    const float* query      = (const float*)d_in[0];
    const float* key        = (const float*)d_in[1];
    const float* value      = (const float*)d_in[2];
    const float* Wq         = (const float*)d_in[3];
    const float* bq         = (const float*)d_in[4];
    const float* Wk         = (const float*)d_in[5];
    const float* bk         = (const float*)d_in[6];
    const float* Wv         = (const float*)d_in[7];
    const float* bv         = (const float*)d_in[8];
    const float* bias_table = (const float*)d_in[9];
    const float* Wp         = (const float*)d_in[10];
    const float* bp         = (const float*)d_in[11];
    const float* mask       = (const float*)d_in[12];
    const int*   rel_index  = (const int*)d_in[13];
    float* out = (float*)d_out;

    __half* q = nullptr; __half* k = nullptr; __half* v = nullptr;
    cudaGetSymbolAddress((void**)&q,  g_q);
    cudaGetSymbolAddress((void**)&k,  g_k);
    cudaGetSymbolAddress((void**)&v,  g_v);

    cudaFuncSetAttribute(proj_kernel,
                         cudaFuncAttributeMaxDynamicSharedMemorySize, PROJ_SMEM);
    cudaFuncSetAttribute(attn_proj_kernel,
                         cudaFuncAttributeMaxDynamicSharedMemorySize, ATTN_SMEM);

    biasfrag_kernel<<<(NWIN * HEADS * 4 * 2 * 8 * 32) / 256, 256>>>(
        bias_table, rel_index, mask);

    proj_kernel<<<dim3(NROWS / 128, 3), 256, PROJ_SMEM>>>(
        query, key, value, Wq, Wk, Wv, bq, bk, bv, q, k, v,
        QSCALE, 1.f, 1.f);

    attn_proj_kernel<<<NBLK, 256, ATTN_SMEM>>>(q, k, v, Wp, bp, out);
}

// round 12
// speedup vs baseline: 3.6309x; 1.4773x over previous
#include <cuda_runtime.h>
#include <cuda_fp16.h>
#include <cstdint>

#define NTOK 49
#define MPAD 64
#define DIM 128
#define HEADS 4
#define HD 32
#define NWIN 64
#define NBLK 4096
#define NROWS (NBLK * NTOK)          // 200704

// half2-unit strides (conflict-free: 4g+tg pattern)
#define SH 68    // q/k/x/w/o tiles: row = 64 data half2 + 4 pad
#define SVT 36   // V^T tile: row = 32 data half2 + 4 pad

// ---------------- global scratch (allocation-free) ----------------
__device__ __half g_q[NROWS * DIM];
__device__ __half g_k[NROWS * DIM];
__device__ __half g_v[NROWS * DIM];
// fused (relbias + mask) in mma C-fragment layout: [win][h][mg][rs][nt][lane]
__device__ float2 g_biasF[NWIN * HEADS * 4 * 2 * 8 * 32];

__global__ void biasfrag_kernel(const float* __restrict__ bias_table,
                                const int* __restrict__ rel_index,
                                const float* __restrict__ mask)
{
    int idx = blockIdx.x * 256 + threadIdx.x;
    int lane = idx & 31;
    int nt   = (idx >> 5) & 7;
    int rs   = (idx >> 8) & 1;
    int mg   = (idx >> 9) & 3;
    int h    = (idx >> 11) & 3;
    int win  = idx >> 13;
    int g = lane >> 2, tg = lane & 3;
    int r = mg * 16 + rs * 8 + g;
    int c0 = nt * 8 + 2 * tg;

    float2 v;
    if (c0 >= NTOK)      v.x = -1e30f;
    else if (r >= NTOK)  v.x = 0.f;
    else v.x = bias_table[rel_index[r * NTOK + c0] * HEADS + h]
             + mask[(win * NTOK + r) * NTOK + c0];
    int c1 = c0 + 1;
    if (c1 >= NTOK)      v.y = -1e30f;
    else if (r >= NTOK)  v.y = 0.f;
    else v.y = bias_table[rel_index[r * NTOK + c1] * HEADS + h]
             + mask[(win * NTOK + r) * NTOK + c1];

    g_biasF[idx] = v;
}

__device__ __forceinline__ uint32_t h2pack(float x, float y) {
    __half2 h = __floats2half2_rn(x, y);
    return *reinterpret_cast<uint32_t*>(&h);
}

// fp16 mma: D(16x8,f32) += A(16x16,f16) x B(16x8,f16 col-major)
__device__ __forceinline__ void mma16(float c[4], const uint32_t a[4], const uint32_t b[2]) {
    asm volatile(
        "mma.sync.aligned.m16n8k16.row.col.f32.f16.f16.f32 "
        "{%0,%1,%2,%3}, {%4,%5,%6,%7}, {%8,%9}, {%0,%1,%2,%3};\n"
        : "+f"(c[0]), "+f"(c[1]), "+f"(c[2]), "+f"(c[3])
        : "r"(a[0]), "r"(a[1]), "r"(a[2]), "r"(a[3]), "r"(b[0]), "r"(b[1]));
}

// =====================================================================
// Projection GEMM (Q/K/V): fp32 in, fp16 mma, fp16 out.
// M-tile 128. X and FULL W in smem as fp16 (no k-chunking). 2 CTAs/SM.
// =====================================================================
__global__ __launch_bounds__(256, 2)
void proj_kernel(const float* __restrict__ X0, const float* __restrict__ X1,
                 const float* __restrict__ X2,
                 const float* __restrict__ W0_, const float* __restrict__ W1_,
                 const float* __restrict__ W2_,
                 const float* __restrict__ B0_, const float* __restrict__ B1_,
                 const float* __restrict__ B2_,
                 __half* __restrict__ O0_, __half* __restrict__ O1_,
                 __half* __restrict__ O2_,
                 float a0, float a1, float a2)
{
    extern __shared__ uint32_t smu[];
    uint32_t* sX = smu;              // 128 x SH half2
    uint32_t* sW = smu + 128 * SH;   // 128 x SH half2

    const float* X; const float* W; const float* Bb; __half* O; float alpha;
    if (blockIdx.y == 0)      { X = X0; W = W0_; Bb = B0_; O = O0_; alpha = a0; }
    else if (blockIdx.y == 1) { X = X1; W = W1_; Bb = B1_; O = O1_; alpha = a1; }
    else                      { X = X2; W = W2_; Bb = B2_; O = O2_; alpha = a2; }

    const int tid  = threadIdx.x;
    const int warp = tid >> 5, lane = tid & 31;
    const int g = lane >> 2, tg = lane & 3;
    const int mBase = blockIdx.x * 128;

    // ---- stage X and W as fp16 ----
    const float4* gX = reinterpret_cast<const float4*>(X + mBase * DIM);
    const float4* gW = reinterpret_cast<const float4*>(W);
    #pragma unroll
    for (int t = 0; t < 16; t++) {
        int f = t * 256 + tid;
        int r = f >> 5, c4 = f & 31;
        float4 v = gX[f];
        uint2 u = make_uint2(h2pack(v.x, v.y), h2pack(v.z, v.w));
        *reinterpret_cast<uint2*>(&sX[r * SH + 2 * c4]) = u;
        float4 w = gW[f];
        uint2 uw = make_uint2(h2pack(w.x, w.y), h2pack(w.z, w.w));
        *reinterpret_cast<uint2*>(&sW[r * SH + 2 * c4]) = uw;
    }
    __syncthreads();

    const int wm = warp & 3;     // 4 m-chunks of 32 rows
    const int wn = warp >> 2;    // 2 n-chunks of 64 cols
    float acc[2][8][4];
    #pragma unroll
    for (int mt = 0; mt < 2; mt++)
        #pragma unroll
        for (int nt = 0; nt < 8; nt++)
            #pragma unroll
            for (int j = 0; j < 4; j++) acc[mt][nt][j] = 0.f;

    #pragma unroll
    for (int kk = 0; kk < 8; kk++) {
        uint32_t a[2][4];
        #pragma unroll
        for (int mt = 0; mt < 2; mt++) {
            const int ab = (wm * 32 + mt * 16 + g) * SH + kk * 8 + tg;
            a[mt][0] = sX[ab];
            a[mt][1] = sX[ab + 8 * SH];
            a[mt][2] = sX[ab + 4];
            a[mt][3] = sX[ab + 8 * SH + 4];
        }
        #pragma unroll
        for (int nt = 0; nt < 8; nt++) {
            const int bb = (wn * 64 + nt * 8 + g) * SH + kk * 8 + tg;
            uint32_t b[2] = { sW[bb], sW[bb + 4] };
            mma16(acc[0][nt], a[0], b);
            mma16(acc[1][nt], a[1], b);
        }
    }

    // ---- epilogue: bias, alpha, fp16 stores ----
    #pragma unroll
    for (int mt = 0; mt < 2; mt++) {
        const int r0 = mBase + wm * 32 + mt * 16 + g;
        #pragma unroll
        for (int nt = 0; nt < 8; nt++) {
            const int c = wn * 64 + nt * 8 + 2 * tg;
            const float b0 = Bb[c], b1 = Bb[c + 1];
            *reinterpret_cast<uint32_t*>(O + r0 * DIM + c) =
                h2pack((acc[mt][nt][0] + b0) * alpha, (acc[mt][nt][1] + b1) * alpha);
            *reinterpret_cast<uint32_t*>(O + (r0 + 8) * DIM + c) =
                h2pack((acc[mt][nt][2] + b0) * alpha, (acc[mt][nt][3] + b1) * alpha);
        }
    }
}

// =====================================================================
// Fused attention + output projection, all-fp16 mma.
// smem: q[64xSH h2] k[64xSH h2] vT[128xSVT h2] = 52KB. O overlays q;
// whole Wp (fp16) overlays k+vT. 2 CTAs/SM.
// =====================================================================
__global__ __launch_bounds__(256, 2)
void attn_proj_kernel(const __half* __restrict__ gq, const __half* __restrict__ gk,
                      const __half* __restrict__ gv, const float* __restrict__ Wp,
                      const float* __restrict__ bp, float* __restrict__ out)
{
    extern __shared__ uint32_t smu[];
    uint32_t* sQ  = smu;                   // 64 x SH half2  (later: O fp16)
    uint32_t* sK  = smu + MPAD * SH;       // 64 x SH half2  (later: Wp)
    uint32_t* sVT = sK + MPAD * SH;        // 128 x SVT half2
    unsigned short* sVTus = reinterpret_cast<unsigned short*>(sVT);

    const int tid = threadIdx.x;
    const int warp = tid >> 5, lane = tid & 31;
    const int g = lane >> 2, tg = lane & 3;
    const int b = blockIdx.x;
    const int base = b * NTOK * DIM;

    // ---- phase 0: zero vT fully + q/k pad rows (tokens 49..63) ----
    {
        uint4 z = make_uint4(0, 0, 0, 0);
        uint4* zv = reinterpret_cast<uint4*>(sVT);
        #pragma unroll
        for (int t = 0; t < 5; t++) {
            int i = t * 256 + tid;
            if (i < 128 * SVT / 4) zv[i] = z;       // 1152 uint4
        }
        if (tid < 255) {                            // 15 rows x 17 uint4
            int row = 49 + tid / 17, c = tid % 17;
            reinterpret_cast<uint4*>(sQ)[row * 17 + c] = z;
            reinterpret_cast<uint4*>(sK)[row * 17 + c] = z;
        }
    }
    __syncthreads();

    // ---- phase 1: stage q/k (raw copy) + v (transpose) ----
    {
        const uint4* Gq = reinterpret_cast<const uint4*>(gq + base);
        const uint4* Gk = reinterpret_cast<const uint4*>(gk + base);
        const uint4* Gv = reinterpret_cast<const uint4*>(gv + base);
        uint4 rq[3], rk[3], rv[3], tq, tk, tv;
        const bool hasTail = tid < 16;
        if (hasTail) { tq = Gq[768 + tid]; tk = Gk[768 + tid]; tv = Gv[768 + tid]; }
        #pragma unroll
        for (int t = 0; t < 3; t++) rq[t] = Gq[t * 256 + tid];
        #pragma unroll
        for (int t = 0; t < 3; t++) rk[t] = Gk[t * 256 + tid];
        #pragma unroll
        for (int t = 0; t < 3; t++) rv[t] = Gv[t * 256 + tid];

        uint4* q4 = reinterpret_cast<uint4*>(sQ);
        uint4* k4 = reinterpret_cast<uint4*>(sK);
        #pragma unroll
        for (int t = 0; t < 3; t++) {
            int f = t * 256 + tid;
            int r = f >> 4, c16 = f & 15;
            q4[r * 17 + c16] = rq[t];
            k4[r * 17 + c16] = rk[t];
            // transpose v: 8 halves (dims c16*8..+7 of token r) -> sVT[dim][r]
            uint32_t w[4] = { rv[t].x, rv[t].y, rv[t].z, rv[t].w };
            int d0 = c16 * 8;
            #pragma unroll
            for (int j = 0; j < 4; j++) {
                sVTus[(d0 + 2 * j) * (2 * SVT) + r]     = (unsigned short)(w[j] & 0xffff);
                sVTus[(d0 + 2 * j + 1) * (2 * SVT) + r] = (unsigned short)(w[j] >> 16);
            }
        }
        if (hasTail) {
            int f = 768 + tid;
            int r = f >> 4, c16 = f & 15;       // row 48
            q4[r * 17 + c16] = tq;
            k4[r * 17 + c16] = tk;
            uint32_t w[4] = { tv.x, tv.y, tv.z, tv.w };
            int d0 = c16 * 8;
            #pragma unroll
            for (int j = 0; j < 4; j++) {
                sVTus[(d0 + 2 * j) * (2 * SVT) + r]     = (unsigned short)(w[j] & 0xffff);
                sVTus[(d0 + 2 * j + 1) * (2 * SVT) + r] = (unsigned short)(w[j] >> 16);
            }
        }
    }
    __syncthreads();

    const float2* bwin = g_biasF + (size_t)(b & (NWIN - 1)) * (HEADS * 4 * 2 * 8 * 32);

    float accO[2][4][4];
    #pragma unroll
    for (int task = 0; task < 2; task++)
        #pragma unroll
        for (int nt = 0; nt < 4; nt++)
            #pragma unroll
            for (int j = 0; j < 4; j++) accO[task][nt][j] = 0.f;

    #pragma unroll
    for (int task = 0; task < 2; task++) {
        const int rg = task * 8 + warp;        // 0..15
        const int h  = rg >> 2;
        const int mg = rg & 3;
        const int mB = mg * 16;

        // ---- S = q_h @ k_h^T: 16x64, k=32 (2 mma k-steps) ----
        float accS[8][4];
        #pragma unroll
        for (int nt = 0; nt < 8; nt++)
            #pragma unroll
            for (int j = 0; j < 4; j++) accS[nt][j] = 0.f;

        #pragma unroll
        for (int kk = 0; kk < 2; kk++) {
            uint32_t a[4];
            const int ab = (mB + g) * SH + h * 16 + kk * 8 + tg;
            a[0] = sQ[ab];
            a[1] = sQ[ab + 8 * SH];
            a[2] = sQ[ab + 4];
            a[3] = sQ[ab + 8 * SH + 4];
            #pragma unroll
            for (int nt = 0; nt < 8; nt++) {
                const int bb = (nt * 8 + g) * SH + h * 16 + kk * 8 + tg;
                uint32_t bfr[2] = { sK[bb], sK[bb + 4] };
                mma16(accS[nt], a, bfr);
            }
        }

        // ---- fused bias fragments (16 coalesced LDG.64) ----
        const float2* bfp = bwin + ((h * 4 + mg) * 2 * 8) * 32 + lane;
        float2 bR[2][8];
        #pragma unroll
        for (int rs = 0; rs < 2; rs++)
            #pragma unroll
            for (int nt = 0; nt < 8; nt++)
                bR[rs][nt] = bfp[(rs * 8 + nt) * 32];

        // ---- bias + softmax in-register; accS becomes P ----
        #pragma unroll
        for (int rs = 0; rs < 2; rs++) {
            float lv[16];
            #pragma unroll
            for (int nt = 0; nt < 8; nt++) {
                lv[nt * 2 + 0] = accS[nt][rs * 2 + 0] + bR[rs][nt].x;
                lv[nt * 2 + 1] = accS[nt][rs * 2 + 1] + bR[rs][nt].y;
            }
            float m = lv[0];
            #pragma unroll
            for (int i = 1; i < 16; i++) m = fmaxf(m, lv[i]);
            m = fmaxf(m, __shfl_xor_sync(0xffffffffu, m, 1));
            m = fmaxf(m, __shfl_xor_sync(0xffffffffu, m, 2));
            float s = 0.f;
            #pragma unroll
            for (int i = 0; i < 16; i++) { lv[i] = __expf(lv[i] - m); s += lv[i]; }
            s += __shfl_xor_sync(0xffffffffu, s, 1);
            s += __shfl_xor_sync(0xffffffffu, s, 2);
            const float inv = 1.f / s;
            #pragma unroll
            for (int nt = 0; nt < 8; nt++) {
                accS[nt][rs * 2 + 0] = lv[nt * 2 + 0] * inv;
                accS[nt][rs * 2 + 1] = lv[nt * 2 + 1] * inv;
            }
        }

        // ---- O = P @ V_h: A-frags by packing C-frags (no shuffles) ----
        #pragma unroll
        for (int kk = 0; kk < 4; kk++) {       // 64 tokens = 4 k16 steps
            uint32_t a[4];
            a[0] = h2pack(accS[2 * kk][0],     accS[2 * kk][1]);
            a[1] = h2pack(accS[2 * kk][2],     accS[2 * kk][3]);
            a[2] = h2pack(accS[2 * kk + 1][0], accS[2 * kk + 1][1]);
            a[3] = h2pack(accS[2 * kk + 1][2], accS[2 * kk + 1][3]);
            #pragma unroll
            for (int nt = 0; nt < 4; nt++) {
                const int bb = (h * HD + nt * 8 + g) * SVT + kk * 8 + tg;
                uint32_t bfr[2] = { sVT[bb], sVT[bb + 4] };
                mma16(accO[task][nt], a, bfr);
            }
        }
    }
    __syncthreads();   // done reading q/k/vT

    // ---- O tile (fp16) into sQ region; whole Wp (fp16) into sK.. ----
    #pragma unroll
    for (int task = 0; task < 2; task++) {
        const int rg = task * 8 + warp;
        const int h  = rg >> 2;
        const int mB = (rg & 3) * 16;
        #pragma unroll
        for (int nt = 0; nt < 4; nt++) {
            const int c2 = h * 16 + nt * 4 + tg;   // half2 col index
            sQ[(mB + g) * SH + c2]     = h2pack(accO[task][nt][0], accO[task][nt][1]);
            sQ[(mB + 8 + g) * SH + c2] = h2pack(accO[task][nt][2], accO[task][nt][3]);
        }
    }
    uint32_t* sWp = sK;    // 128 x SH half2 = 8704 words (fits in sK+sVT = 8960)
    {
        const float4* gW = reinterpret_cast<const float4*>(Wp);
        #pragma unroll
        for (int t = 0; t < 16; t++) {
            int f = t * 256 + tid;
            int r = f >> 5, c4 = f & 31;
            float4 w = gW[f];
            uint2 uw = make_uint2(h2pack(w.x, w.y), h2pack(w.z, w.w));
            *reinterpret_cast<uint2*>(&sWp[r * SH + 2 * c4]) = uw;
        }
    }
    __syncthreads();

    // ---- out[64,128] = O @ Wp^T + bp ----
    const int wm = warp & 3;     // rows 16*wm
    const int wn = warp >> 2;    // cols 64*wn
    float acc2[8][4];
    #pragma unroll
    for (int nt = 0; nt < 8; nt++)
        #pragma unroll
        for (int j = 0; j < 4; j++) acc2[nt][j] = 0.f;

    #pragma unroll
    for (int kk = 0; kk < 8; kk++) {
        uint32_t a[4];
        const int ab = (wm * 16 + g) * SH + kk * 8 + tg;
        a[0] = sQ[ab];
        a[1] = sQ[ab + 8 * SH];
        a[2] = sQ[ab + 4];
        a[3] = sQ[ab + 8 * SH + 4];
        #pragma unroll
        for (int nt = 0; nt < 8; nt++) {
            const int bb = (wn * 64 + nt * 8 + g) * SH + kk * 8 + tg;
            uint32_t bfr[2] = { sWp[bb], sWp[bb + 4] };
            mma16(acc2[nt], a, bfr);
        }
    }

    const int r0 = wm * 16 + g, r1 = r0 + 8;
    #pragma unroll
    for (int nt = 0; nt < 8; nt++) {
        const int c = wn * 64 + nt * 8 + 2 * tg;
        const float b0 = bp[c], b1 = bp[c + 1];
        if (r0 < NTOK)
            *reinterpret_cast<float2*>(out + base + r0 * DIM + c) =
                make_float2(acc2[nt][0] + b0, acc2[nt][1] + b1);
        if (r1 < NTOK)
            *reinterpret_cast<float2*>(out + base + r1 * DIM + c) =
                make_float2(acc2[nt][2] + b0, acc2[nt][3] + b1);
    }
}

#define PROJ_SMEM (2 * 128 * SH * 4)                       // 69632 B
#define ATTN_SMEM ((2 * MPAD * SH + 128 * SVT) * 4)        // 53248 B
#define QSCALE 0.17677669529663687f

extern "C" void kernel_launch(void* const* d_in, const int* in_sizes, int n_in,
                              void* d_out, int out_size)
{
    const float* query      = (const float*)d_in[0];
    const float* key        = (const float*)d_in[1];
    const float* value      = (const float*)d_in[2];
    const float* Wq         = (const float*)d_in[3];
    const float* bq         = (const float*)d_in[4];
    const float* Wk         = (const float*)d_in[5];
    const float* bk         = (const float*)d_in[6];
    const float* Wv         = (const float*)d_in[7];
    const float* bv         = (const float*)d_in[8];
    const float* bias_table = (const float*)d_in[9];
    const float* Wp         = (const float*)d_in[10];
    const float* bp         = (const float*)d_in[11];
    const float* mask       = (const float*)d_in[12];
    const int*   rel_index  = (const int*)d_in[13];
    float* out = (float*)d_out;

    __half* q = nullptr; __half* k = nullptr; __half* v = nullptr;
    cudaGetSymbolAddress((void**)&q,  g_q);
    cudaGetSymbolAddress((void**)&k,  g_k);
    cudaGetSymbolAddress((void**)&v,  g_v);

    cudaFuncSetAttribute(proj_kernel,
                         cudaFuncAttributeMaxDynamicSharedMemorySize, PROJ_SMEM);
    cudaFuncSetAttribute(attn_proj_kernel,
                         cudaFuncAttributeMaxDynamicSharedMemorySize, ATTN_SMEM);

    biasfrag_kernel<<<(NWIN * HEADS * 4 * 2 * 8 * 32) / 256, 256>>>(
        bias_table, rel_index, mask);

    proj_kernel<<<dim3(NROWS / 128, 3), 256, PROJ_SMEM>>>(
        query, key, value, Wq, Wk, Wv, bq, bk, bv, q, k, v,
        QSCALE, 1.f, 1.f);

    attn_proj_kernel<<<NBLK, 256, ATTN_SMEM>>>(q, k, v, Wp, bp, out);
}